// round 4
// baseline (speedup 1.0000x reference)
#include <cuda_runtime.h>

#define H      64
#define E_PER  300000
#define RTOT   9
#define ETOT   (RTOT * E_PER)
#define NB     64
#define N0     100000
#define N1     20000
#define N2     50000
#define N3     80000
#define NTOT   250000
#define NMAX   100000
#define NDSUM  660000   // sum of Nd over relations

// ---------------- static device scratch ----------------
__device__ float g_feat0[NTOT * H];
__device__ float g_feat1[NTOT * H];
__device__ float g_tmp[(size_t)RTOT * NMAX * H];   // per-relation aggregated src feats
__device__ float g_als[RTOT * NMAX];
__device__ float g_ald[RTOT * NMAX];
__device__ float g_wsv[RTOT * H];
__device__ float g_wdv[RTOT * H];
__device__ float g_pool[NB * 2 * H];
__device__ float g_cnt[2 * NB];
// CSR (built once per launch; edges are constant inputs)
__device__ int   g_deg[RTOT * NMAX];
__device__ int   g_off[RTOT * NMAX];
__device__ int   g_cur[RTOT * NMAX];
__device__ int   g_cursor[RTOT];
__device__ int   g_csrc[ETOT];

__constant__ int c_ST[9]  = {0, 0, 0, 2, 3, 1, 2, 3, 3};
__constant__ int c_DT[9]  = {1, 2, 3, 3, 3, 0, 0, 0, 2};
__constant__ int c_NSZ[4] = {N0, N1, N2, N3};
__constant__ int c_OFF[4] = {0, N0, N0 + N1, N0 + N1 + N2};
// cumulative Nd per relation (warp->relation lookup in gather)
__constant__ int c_DOFF[10] = {0, 20000, 70000, 150000, 230000, 310000,
                               410000, 510000, 610000, 660000};
// relations targeting type t, -1 padded
__constant__ int c_TB[4][3] = {{5, 6, 7}, {0, -1, -1}, {1, 8, -1}, {2, 3, 4}};

struct XP { const float* x[4]; };
struct EP { const int* s[9]; const int* d[9]; };

// ---------------------------- tf32 helpers ----------------------------
__device__ __forceinline__ unsigned f2tf(float f) {
    unsigned u;
    asm("cvt.rna.tf32.f32 %0, %1;" : "=r"(u) : "f"(f));
    return u;
}
__device__ __forceinline__ void mma8(float* c, const unsigned* a, unsigned b0, unsigned b1) {
    asm volatile(
        "mma.sync.aligned.m16n8k8.row.col.f32.tf32.tf32.f32 "
        "{%0,%1,%2,%3},{%4,%5,%6,%7},{%8,%9},{%0,%1,%2,%3};"
        : "+f"(c[0]), "+f"(c[1]), "+f"(c[2]), "+f"(c[3])
        : "r"(a[0]), "r"(a[1]), "r"(a[2]), "r"(a[3]), "r"(b0), "r"(b1));
}

// ------------------------------- CSR build (once) -------------------------------
__global__ void csr_zero() {
    int i = blockIdx.x * blockDim.x + threadIdx.x;
    if (i < RTOT * NMAX) { g_deg[i] = 0; g_cur[i] = 0; }
    if (i < RTOT) g_cursor[i] = 0;
}

__global__ void csr_hist(EP ep) {
    int idx = blockIdx.x * blockDim.x + threadIdx.x;
    if (idx >= ETOT) return;
    int r = idx / E_PER, e = idx - r * E_PER;
    atomicAdd(&g_deg[r * NMAX + __ldg(&ep.d[r][e])], 1);
}

// warp-aggregated offset assignment (list order within a relation is irrelevant)
__global__ void csr_assign() {
    int i = blockIdx.x * blockDim.x + threadIdx.x;
    if (i >= RTOT * NMAX) return;
    int lane = threadIdx.x & 31;
    int r = i / NMAX;                      // NMAX % 32 == 0: warp stays in one r
    int deg = g_deg[i];
    int v = deg;
    #pragma unroll
    for (int o = 1; o < 32; o <<= 1) {
        int t = __shfl_up_sync(0xffffffffu, v, o);
        if (lane >= o) v += t;
    }
    int total = __shfl_sync(0xffffffffu, v, 31);
    int base = 0;
    if (lane == 31) base = atomicAdd(&g_cursor[r], total);
    base = __shfl_sync(0xffffffffu, base, 31);
    g_off[i] = base + v - deg;
}

__global__ void csr_fill(EP ep) {
    int idx = blockIdx.x * blockDim.x + threadIdx.x;
    if (idx >= ETOT) return;
    int r = idx / E_PER, e = idx - r * E_PER;
    int d = __ldg(&ep.d[r][e]);
    int pos = atomicAdd(&g_cur[r * NMAX + d], 1);
    g_csrc[r * E_PER + g_off[r * NMAX + d] + pos] = __ldg(&ep.s[r][e]);
}

// ---------------------------------- per-layer -----------------------------------

// block r: wsv[r][k] = sum_j Wsrc[r][k][j]*asrc[r][j]; same for dst
__global__ void prep(const float* __restrict__ Ws_l, const float* __restrict__ as_l,
                     const float* __restrict__ Wd_l, const float* __restrict__ ad_l) {
    int r = blockIdx.x, t = threadIdx.x;
    const float* W; const float* a; float* o; int k;
    if (t < 64) { W = Ws_l + r * 4096; a = as_l + r * 64; o = g_wsv + r * 64; k = t; }
    else        { W = Wd_l + r * 4096; a = ad_l + r * 64; o = g_wdv + r * 64; k = t - 64; }
    float s = 0.f;
    #pragma unroll
    for (int j = 0; j < 64; j++) s += W[k * 64 + j] * a[j];
    o[k] = s;
}

// warp per node: attention logits for every (relation, side) of its type
__global__ void alpha_all(XP xp, int use_feat) {
    int warp = threadIdx.x >> 5, lane = threadIdx.x & 31;
    int gw = blockIdx.x * 8 + warp;
    if (gw >= NTOT) return;
    int t = (gw < N0) ? 0 : (gw < N0 + N1) ? 1 : (gw < N0 + N1 + N2) ? 2 : 3;
    int li = gw - c_OFF[t];
    const float* x = use_feat ? (g_feat0 + (size_t)c_OFF[t] * H) : xp.x[t];
    float x0 = x[(size_t)li * H + lane];
    float x1 = x[(size_t)li * H + 32 + lane];
    if (use_feat) { x0 = fmaxf(x0, 0.f); x1 = fmaxf(x1, 0.f); }
    #pragma unroll
    for (int r = 0; r < 9; r++) {
        if (c_ST[r] == t) {
            float v = x0 * g_wsv[r * 64 + lane] + x1 * g_wsv[r * 64 + 32 + lane];
            #pragma unroll
            for (int o = 16; o; o >>= 1) v += __shfl_xor_sync(0xffffffffu, v, o);
            if (lane == 0) g_als[r * NMAX + li] = v;
        }
        if (c_DT[r] == t) {
            float v = x0 * g_wdv[r * 64 + lane] + x1 * g_wdv[r * 64 + 32 + lane];
            #pragma unroll
            for (int o = 16; o; o >>= 1) v += __shfl_xor_sync(0xffffffffu, v, o);
            if (lane == 0) g_ald[r * NMAX + li] = v;
        }
    }
}

// warp per (relation, dst node): softmax + weighted aggregation of x_act[src]
// tmp[r][d] = sum_e exp(leaky(als[s]+ald[d])) * x_act[s]  /  (z + 1e-16)
__global__ void __launch_bounds__(256) gather(XP xp, int use_feat) {
    int warp = threadIdx.x >> 5, lane = threadIdx.x & 31;
    int gw = blockIdx.x * 8 + warp;
    if (gw >= NDSUM) return;
    int r = 0;
    #pragma unroll
    for (int i = 1; i < 9; i++) if (gw >= c_DOFF[i]) r = i;
    int d = gw - c_DOFF[r];
    int st = c_ST[r];
    const float* x = use_feat ? (g_feat0 + (size_t)c_OFF[st] * H) : xp.x[st];
    float ald = g_ald[r * NMAX + d];
    int beg = g_off[r * NMAX + d];
    int deg = g_deg[r * NMAX + d];
    const int* sl = g_csrc + r * E_PER + beg;
    const float* als = g_als + r * NMAX;

    float2 acc = make_float2(0.f, 0.f);
    float z = 0.f;
    for (int i = 0; i < deg; i++) {
        int s = __ldg(&sl[i]);                       // warp-broadcast
        float sc = __ldg(&als[s]) + ald;
        sc = sc > 0.f ? sc : 0.2f * sc;
        float p = __expf(sc);
        z += p;
        float2 v = *(const float2*)(x + (size_t)s * H + lane * 2);
        if (use_feat) { v.x = fmaxf(v.x, 0.f); v.y = fmaxf(v.y, 0.f); }
        acc.x += p * v.x;
        acc.y += p * v.y;
    }
    float inv = __fdividef(1.f, z + 1e-16f);
    float2* o = (float2*)(g_tmp + (size_t)r * NMAX * H + (size_t)d * H);
    o[lane] = make_float2(acc.x * inv, acc.y * inv);
}

// feat[dtype] = sum_{r->dtype} tmp_r @ Wsrc_r + sum bias_r
// grid.y = dst type; register accumulation across relations; tf32 3-term mma
__global__ void __launch_bounds__(128) gemm_out(const float* __restrict__ Ws_l,
                                                const float* __restrict__ bias_l,
                                                int outbuf) {
    __shared__ float sA[64 * 72];
    __shared__ float sW[64 * 72];
    __shared__ float sBias[64];
    int g = blockIdx.y;
    int Nd = c_NSZ[g];
    int row0 = blockIdx.x * 64;
    if (row0 >= Nd) return;
    int tid = threadIdx.x;

    if (tid < 64) {
        float s = 0.f;
        #pragma unroll
        for (int i = 0; i < 3; i++) {
            int r = c_TB[g][i];
            if (r >= 0) s += bias_l[r * 64 + tid];
        }
        sBias[tid] = s;
    }

    int warp = tid >> 5, lane = tid & 31;
    int gid = lane >> 2, tig = lane & 3;
    int mrow = warp * 16;

    float acc[8][4];
    #pragma unroll
    for (int n = 0; n < 8; n++)
        #pragma unroll
        for (int j = 0; j < 4; j++) acc[n][j] = 0.f;

    #pragma unroll
    for (int ri = 0; ri < 3; ri++) {
        int r = c_TB[g][ri];
        if (r < 0) break;
        __syncthreads();
        const float4* A4 = (const float4*)(g_tmp + (size_t)r * NMAX * H);
        #pragma unroll
        for (int i = 0; i < 8; i++) {
            int idx = tid + i * 128;
            int rr = idx >> 4, c4 = idx & 15;
            float4 v = make_float4(0.f, 0.f, 0.f, 0.f);
            if (row0 + rr < Nd) v = A4[(size_t)(row0 + rr) * 16 + c4];
            float* dst = sA + rr * 72 + c4 * 4;
            dst[0] = v.x; dst[1] = v.y; dst[2] = v.z; dst[3] = v.w;
        }
        const float4* W4 = (const float4*)(Ws_l + (size_t)r * 4096);
        #pragma unroll
        for (int i = 0; i < 8; i++) {
            int idx = tid + i * 128;
            int rr = idx >> 4, c4 = idx & 15;
            float4 v = W4[idx];
            float* dst = sW + rr * 72 + c4 * 4;
            dst[0] = v.x; dst[1] = v.y; dst[2] = v.z; dst[3] = v.w;
        }
        __syncthreads();

        #pragma unroll
        for (int k0 = 0; k0 < 8; k0++) {
            float af[4];
            af[0] = sA[(mrow + gid)     * 72 + k0 * 8 + tig];
            af[1] = sA[(mrow + gid + 8) * 72 + k0 * 8 + tig];
            af[2] = sA[(mrow + gid)     * 72 + k0 * 8 + tig + 4];
            af[3] = sA[(mrow + gid + 8) * 72 + k0 * 8 + tig + 4];
            unsigned as_[4], ar_[4];
            #pragma unroll
            for (int j = 0; j < 4; j++) {
                as_[j] = f2tf(af[j]);
                ar_[j] = f2tf(af[j] - __uint_as_float(as_[j]));
            }
            #pragma unroll
            for (int n0 = 0; n0 < 8; n0++) {
                float bf0 = sW[(k0 * 8 + tig)     * 72 + n0 * 8 + gid];
                float bf1 = sW[(k0 * 8 + tig + 4) * 72 + n0 * 8 + gid];
                unsigned bs0 = f2tf(bf0), bs1 = f2tf(bf1);
                unsigned br0 = f2tf(bf0 - __uint_as_float(bs0));
                unsigned br1 = f2tf(bf1 - __uint_as_float(bs1));
                mma8(acc[n0], as_, bs0, bs1);
                mma8(acc[n0], ar_, bs0, bs1);
                mma8(acc[n0], as_, br0, br1);
            }
        }
    }

    float* fb = ((outbuf == 0) ? g_feat0 : g_feat1) + (size_t)c_OFF[g] * H;
    int rr0 = row0 + mrow + gid;
    int rr1 = rr0 + 8;
    #pragma unroll
    for (int n0 = 0; n0 < 8; n0++) {
        int cc = n0 * 8 + 2 * tig;
        float b0 = sBias[cc], b1 = sBias[cc + 1];
        if (rr0 < Nd) {
            float2* p = (float2*)(fb + (size_t)rr0 * H + cc);
            *p = make_float2(acc[n0][0] + b0, acc[n0][1] + b1);
        }
        if (rr1 < Nd) {
            float2* p = (float2*)(fb + (size_t)rr1 * H + cc);
            *p = make_float2(acc[n0][2] + b0, acc[n0][3] + b1);
        }
    }
}

// ---------------------------------- pooling -------------------------------------
__global__ void pool_zero() {
    int i = blockIdx.x * blockDim.x + threadIdx.x;
    if (i < NB * 2 * H) g_pool[i] = 0.f;
    if (i < 2 * NB)     g_cnt[i]  = 0.f;
}

__global__ void pool_kernel(const int* __restrict__ bvar, const int* __restrict__ bcon) {
    int warp = threadIdx.x >> 5, lane = threadIdx.x & 31;
    int gw = blockIdx.x * 8 + warp;
    if (gw < N0) {
        int b = bvar[gw];
        size_t base = (size_t)gw * H;
        atomicAdd(&g_pool[b * 128 + lane],      fmaxf(g_feat1[base + lane], 0.f));
        atomicAdd(&g_pool[b * 128 + 32 + lane], fmaxf(g_feat1[base + 32 + lane], 0.f));
        if (lane == 0) atomicAdd(&g_cnt[b], 1.f);
    } else if (gw < N0 + N3) {
        int j = gw - N0;
        int b = bcon[j];
        const float* xc = g_feat1 + (size_t)(N0 + N1 + N2) * H;
        size_t base = (size_t)j * H;
        atomicAdd(&g_pool[b * 128 + 64 + lane], fmaxf(xc[base + lane], 0.f));
        atomicAdd(&g_pool[b * 128 + 96 + lane], fmaxf(xc[base + 32 + lane], 0.f));
        if (lane == 0) atomicAdd(&g_cnt[NB + b], 1.f);
    }
}

__global__ void final_kernel(const float* __restrict__ lw, const float* __restrict__ lb,
                             float* __restrict__ out) {
    int t = threadIdx.x;
    if (t >= 128) return;
    int b = t >> 1, o = t & 1;
    float cv = fmaxf(g_cnt[b], 1.f);
    float cc = fmaxf(g_cnt[NB + b], 1.f);
    float s = lb[o];
    #pragma unroll
    for (int j = 0; j < H; j++) {
        s += (g_pool[b * 128 + j]      / cv) * lw[o * 128 + j];
        s += (g_pool[b * 128 + 64 + j] / cc) * lw[o * 128 + 64 + j];
    }
    out[b * 2 + o] = s;
}

// ---------------------------------- launcher -------------------------------------
extern "C" void kernel_launch(void* const* d_in, const int* in_sizes, int n_in,
                              void* d_out, int out_size) {
    XP xp;
    for (int t = 0; t < 4; t++) xp.x[t] = (const float*)d_in[t];
    const float* Wsrc = (const float*)d_in[4];
    const float* Wdst = (const float*)d_in[5];
    const float* asrc = (const float*)d_in[6];
    const float* adst = (const float*)d_in[7];
    const float* bias = (const float*)d_in[8];
    const float* lw   = (const float*)d_in[9];
    const float* lb   = (const float*)d_in[10];
    EP ep;
    for (int r = 0; r < 9; r++) {
        ep.s[r] = (const int*)d_in[11 + 2 * r];
        ep.d[r] = (const int*)d_in[12 + 2 * r];
    }
    const int* bvar = (const int*)d_in[29];
    const int* bcon = (const int*)d_in[30];

    // CSR build (edges are constant; rebuilt identically every call)
    csr_zero<<<(RTOT * NMAX + 255) / 256, 256>>>();
    csr_hist<<<(ETOT + 255) / 256, 256>>>(ep);
    csr_assign<<<(RTOT * NMAX + 255) / 256, 256>>>();
    csr_fill<<<(ETOT + 255) / 256, 256>>>(ep);

    for (int l = 0; l < 2; l++) {
        const float* Ws_l = Wsrc + (size_t)l * 9 * 4096;
        const float* Wd_l = Wdst + (size_t)l * 9 * 4096;
        const float* as_l = asrc + (size_t)l * 9 * 64;
        const float* ad_l = adst + (size_t)l * 9 * 64;
        const float* b_l  = bias + (size_t)l * 9 * 64;

        prep<<<9, 128>>>(Ws_l, as_l, Wd_l, ad_l);
        alpha_all<<<(NTOT + 7) / 8, 256>>>(xp, l);
        gather<<<(NDSUM + 7) / 8, 256>>>(xp, l);
        gemm_out<<<dim3((NMAX + 63) / 64, 4), 128>>>(Ws_l, b_l, l);
    }
    pool_zero<<<(NB * 2 * H + 255) / 256, 256>>>();
    pool_kernel<<<(N0 + N3 + 7) / 8, 256>>>(bvar, bcon);
    final_kernel<<<1, 128>>>(lw, lb, (float*)d_out);
}

// round 5
// speedup vs baseline: 1.1020x; 1.1020x over previous
#include <cuda_runtime.h>

#define H      64
#define E_PER  300000
#define RTOT   9
#define ETOT   (RTOT * E_PER)
#define NB     64
#define N0     100000
#define N1     20000
#define N2     50000
#define N3     80000
#define NTOT   250000
#define NMAX   100000
#define NDSUM  660000   // sum of Nd over relations

// ---------------- static device scratch ----------------
__device__ float g_feat0[NTOT * H];
__device__ float g_feat1[NTOT * H];
__device__ float g_tmp[(size_t)RTOT * NMAX * H];   // per-relation aggregated src feats
__device__ float g_als[RTOT * NMAX];
__device__ float g_ald[RTOT * NMAX];
__device__ float g_wsv[2 * RTOT * H];              // both layers
__device__ float g_wdv[2 * RTOT * H];
__device__ float g_pool[NB * 2 * H];
__device__ float g_cnt[2 * NB];
// CSR (built once per launch; edges are constant inputs)
__device__ int   g_deg[RTOT * NMAX];
__device__ int   g_off[RTOT * NMAX];
__device__ int   g_cur[RTOT * NMAX];
__device__ int   g_cursor[RTOT];
__device__ int   g_csrc[ETOT];

__constant__ int c_ST[9]  = {0, 0, 0, 2, 3, 1, 2, 3, 3};
__constant__ int c_DT[9]  = {1, 2, 3, 3, 3, 0, 0, 0, 2};
__constant__ int c_NSZ[4] = {N0, N1, N2, N3};
__constant__ int c_OFF[4] = {0, N0, N0 + N1, N0 + N1 + N2};
// cumulative Nd per relation (warp->relation lookup in gather)
__constant__ int c_DOFF[10] = {0, 20000, 70000, 150000, 230000, 310000,
                               410000, 510000, 610000, 660000};
// relations targeting type t, -1 padded
__constant__ int c_TB[4][3] = {{5, 6, 7}, {0, -1, -1}, {1, 8, -1}, {2, 3, 4}};

struct XP { const float* x[4]; };
struct EP { const int* s[9]; const int* d[9]; };

// ---------------------------- tf32 helpers ----------------------------
__device__ __forceinline__ unsigned f2tf(float f) {
    unsigned u;
    asm("cvt.rna.tf32.f32 %0, %1;" : "=r"(u) : "f"(f));
    return u;
}
__device__ __forceinline__ void mma8(float* c, const unsigned* a, unsigned b0, unsigned b1) {
    asm volatile(
        "mma.sync.aligned.m16n8k8.row.col.f32.tf32.tf32.f32 "
        "{%0,%1,%2,%3},{%4,%5,%6,%7},{%8,%9},{%0,%1,%2,%3};"
        : "+f"(c[0]), "+f"(c[1]), "+f"(c[2]), "+f"(c[3])
        : "r"(a[0]), "r"(a[1]), "r"(a[2]), "r"(a[3]), "r"(b0), "r"(b1));
}

// ------------------------------- CSR build (once) -------------------------------
__global__ void csr_zero() {
    int i = blockIdx.x * blockDim.x + threadIdx.x;
    if (i < RTOT * NMAX) { g_deg[i] = 0; g_cur[i] = 0; }
    if (i < RTOT) g_cursor[i] = 0;
}

__global__ void csr_hist(EP ep) {
    int idx = blockIdx.x * blockDim.x + threadIdx.x;
    if (idx >= ETOT) return;
    int r = idx / E_PER, e = idx - r * E_PER;
    atomicAdd(&g_deg[r * NMAX + __ldg(&ep.d[r][e])], 1);
}

// warp-aggregated offset assignment (list order within a relation is irrelevant)
__global__ void csr_assign() {
    int i = blockIdx.x * blockDim.x + threadIdx.x;
    if (i >= RTOT * NMAX) return;
    int lane = threadIdx.x & 31;
    int r = i / NMAX;                      // NMAX % 32 == 0: warp stays in one r
    int deg = g_deg[i];
    int v = deg;
    #pragma unroll
    for (int o = 1; o < 32; o <<= 1) {
        int t = __shfl_up_sync(0xffffffffu, v, o);
        if (lane >= o) v += t;
    }
    int total = __shfl_sync(0xffffffffu, v, 31);
    int base = 0;
    if (lane == 31) base = atomicAdd(&g_cursor[r], total);
    base = __shfl_sync(0xffffffffu, base, 31);
    g_off[i] = base + v - deg;
}

__global__ void csr_fill(EP ep) {
    int idx = blockIdx.x * blockDim.x + threadIdx.x;
    if (idx >= ETOT) return;
    int r = idx / E_PER, e = idx - r * E_PER;
    int d = __ldg(&ep.d[r][e]);
    int pos = atomicAdd(&g_cur[r * NMAX + d], 1);
    g_csrc[r * E_PER + g_off[r * NMAX + d] + pos] = __ldg(&ep.s[r][e]);
}

// ---------------------------------- per-layer -----------------------------------

// both layers: block rl in [0,18): wsv[rl][k] = sum_j Wsrc[rl][k][j]*asrc[rl][j]
__global__ void prep(const float* __restrict__ Ws, const float* __restrict__ as_,
                     const float* __restrict__ Wd, const float* __restrict__ ad_) {
    int rl = blockIdx.x, t = threadIdx.x;
    const float* W; const float* a; float* o; int k;
    if (t < 64) { W = Ws + rl * 4096; a = as_ + rl * 64; o = g_wsv + rl * 64; k = t; }
    else        { W = Wd + rl * 4096; a = ad_ + rl * 64; o = g_wdv + rl * 64; k = t - 64; }
    float s = 0.f;
    #pragma unroll
    for (int j = 0; j < 64; j++) s += W[k * 64 + j] * a[j];
    o[k] = s;
}

// warp per node: attention logits for every (relation, side) of its type
__global__ void alpha_all(XP xp, int use_feat, int wbase) {
    int warp = threadIdx.x >> 5, lane = threadIdx.x & 31;
    int gw = blockIdx.x * 8 + warp;
    if (gw >= NTOT) return;
    int t = (gw < N0) ? 0 : (gw < N0 + N1) ? 1 : (gw < N0 + N1 + N2) ? 2 : 3;
    int li = gw - c_OFF[t];
    const float* x = use_feat ? (g_feat0 + (size_t)c_OFF[t] * H) : xp.x[t];
    float x0 = x[(size_t)li * H + lane];
    float x1 = x[(size_t)li * H + 32 + lane];
    if (use_feat) { x0 = fmaxf(x0, 0.f); x1 = fmaxf(x1, 0.f); }
    #pragma unroll
    for (int r = 0; r < 9; r++) {
        if (c_ST[r] == t) {
            float v = x0 * g_wsv[wbase + r * 64 + lane]
                    + x1 * g_wsv[wbase + r * 64 + 32 + lane];
            #pragma unroll
            for (int o = 16; o; o >>= 1) v += __shfl_xor_sync(0xffffffffu, v, o);
            if (lane == 0) g_als[r * NMAX + li] = v;
        }
        if (c_DT[r] == t) {
            float v = x0 * g_wdv[wbase + r * 64 + lane]
                    + x1 * g_wdv[wbase + r * 64 + 32 + lane];
            #pragma unroll
            for (int o = 16; o; o >>= 1) v += __shfl_xor_sync(0xffffffffu, v, o);
            if (lane == 0) g_ald[r * NMAX + li] = v;
        }
    }
}

// warp per (relation, dst node). Index+logit work done lane-parallel (one coalesced
// load per <=32 edges), then shfl-broadcast drives independent row gathers (MLP>=2).
__global__ void __launch_bounds__(256) gather(XP xp, int use_feat) {
    int warp = threadIdx.x >> 5, lane = threadIdx.x & 31;
    int gw = blockIdx.x * 8 + warp;
    if (gw >= NDSUM) return;
    int r = 0;
    #pragma unroll
    for (int i = 1; i < 9; i++) if (gw >= c_DOFF[i]) r = i;
    int d = gw - c_DOFF[r];
    int st = c_ST[r];
    const float* x = use_feat ? (g_feat0 + (size_t)c_OFF[st] * H) : xp.x[st];
    float ald = __ldg(&g_ald[r * NMAX + d]);
    int beg = __ldg(&g_off[r * NMAX + d]);
    int deg = __ldg(&g_deg[r * NMAX + d]);
    const int* sl = g_csrc + r * E_PER + beg;
    const float* als = g_als + r * NMAX;

    float2 acc0 = make_float2(0.f, 0.f), acc1 = make_float2(0.f, 0.f);
    float zl = 0.f;
    for (int base = 0; base < deg; base += 32) {
        int n = min(32, deg - base);
        int idx = 0; float p = 0.f;
        if (lane < n) {
            idx = __ldg(&sl[base + lane]);
            float sc = __ldg(&als[idx]) + ald;
            sc = sc > 0.f ? sc : 0.2f * sc;
            p = __expf(sc);
        }
        zl += p;
        int i = 0;
        for (; i + 2 <= n; i += 2) {
            int   s0 = __shfl_sync(0xffffffffu, idx, i);
            int   s1 = __shfl_sync(0xffffffffu, idx, i + 1);
            float p0 = __shfl_sync(0xffffffffu, p, i);
            float p1 = __shfl_sync(0xffffffffu, p, i + 1);
            float2 v0 = *(const float2*)(x + (size_t)s0 * H + lane * 2);
            float2 v1 = *(const float2*)(x + (size_t)s1 * H + lane * 2);
            if (use_feat) {
                v0.x = fmaxf(v0.x, 0.f); v0.y = fmaxf(v0.y, 0.f);
                v1.x = fmaxf(v1.x, 0.f); v1.y = fmaxf(v1.y, 0.f);
            }
            acc0.x += p0 * v0.x; acc0.y += p0 * v0.y;
            acc1.x += p1 * v1.x; acc1.y += p1 * v1.y;
        }
        if (i < n) {
            int   s0 = __shfl_sync(0xffffffffu, idx, i);
            float p0 = __shfl_sync(0xffffffffu, p, i);
            float2 v0 = *(const float2*)(x + (size_t)s0 * H + lane * 2);
            if (use_feat) { v0.x = fmaxf(v0.x, 0.f); v0.y = fmaxf(v0.y, 0.f); }
            acc0.x += p0 * v0.x; acc0.y += p0 * v0.y;
        }
    }
    float z = zl;
    #pragma unroll
    for (int o = 16; o; o >>= 1) z += __shfl_xor_sync(0xffffffffu, z, o);
    float inv = __fdividef(1.f, z + 1e-16f);
    float2* o2 = (float2*)(g_tmp + (size_t)r * NMAX * H + (size_t)d * H);
    o2[lane] = make_float2((acc0.x + acc1.x) * inv, (acc0.y + acc1.y) * inv);
}

// feat[dtype] = sum_{r->dtype} tmp_r @ Wsrc_r + sum bias_r
__global__ void __launch_bounds__(128) gemm_out(const float* __restrict__ Ws_l,
                                                const float* __restrict__ bias_l,
                                                int outbuf) {
    __shared__ float sA[64 * 72];
    __shared__ float sW[64 * 72];
    __shared__ float sBias[64];
    int g = blockIdx.y;
    int Nd = c_NSZ[g];
    int row0 = blockIdx.x * 64;
    if (row0 >= Nd) return;
    int tid = threadIdx.x;

    if (tid < 64) {
        float s = 0.f;
        #pragma unroll
        for (int i = 0; i < 3; i++) {
            int r = c_TB[g][i];
            if (r >= 0) s += bias_l[r * 64 + tid];
        }
        sBias[tid] = s;
    }

    int warp = tid >> 5, lane = tid & 31;
    int gid = lane >> 2, tig = lane & 3;
    int mrow = warp * 16;

    float acc[8][4];
    #pragma unroll
    for (int n = 0; n < 8; n++)
        #pragma unroll
        for (int j = 0; j < 4; j++) acc[n][j] = 0.f;

    #pragma unroll
    for (int ri = 0; ri < 3; ri++) {
        int r = c_TB[g][ri];
        if (r < 0) break;
        __syncthreads();
        const float4* A4 = (const float4*)(g_tmp + (size_t)r * NMAX * H);
        #pragma unroll
        for (int i = 0; i < 8; i++) {
            int idx = tid + i * 128;
            int rr = idx >> 4, c4 = idx & 15;
            float4 v = make_float4(0.f, 0.f, 0.f, 0.f);
            if (row0 + rr < Nd) v = A4[(size_t)(row0 + rr) * 16 + c4];
            float* dst = sA + rr * 72 + c4 * 4;
            dst[0] = v.x; dst[1] = v.y; dst[2] = v.z; dst[3] = v.w;
        }
        const float4* W4 = (const float4*)(Ws_l + (size_t)r * 4096);
        #pragma unroll
        for (int i = 0; i < 8; i++) {
            int idx = tid + i * 128;
            int rr = idx >> 4, c4 = idx & 15;
            float4 v = W4[idx];
            float* dst = sW + rr * 72 + c4 * 4;
            dst[0] = v.x; dst[1] = v.y; dst[2] = v.z; dst[3] = v.w;
        }
        __syncthreads();

        #pragma unroll
        for (int k0 = 0; k0 < 8; k0++) {
            float af[4];
            af[0] = sA[(mrow + gid)     * 72 + k0 * 8 + tig];
            af[1] = sA[(mrow + gid + 8) * 72 + k0 * 8 + tig];
            af[2] = sA[(mrow + gid)     * 72 + k0 * 8 + tig + 4];
            af[3] = sA[(mrow + gid + 8) * 72 + k0 * 8 + tig + 4];
            unsigned as_[4], ar_[4];
            #pragma unroll
            for (int j = 0; j < 4; j++) {
                as_[j] = f2tf(af[j]);
                ar_[j] = f2tf(af[j] - __uint_as_float(as_[j]));
            }
            #pragma unroll
            for (int n0 = 0; n0 < 8; n0++) {
                float bf0 = sW[(k0 * 8 + tig)     * 72 + n0 * 8 + gid];
                float bf1 = sW[(k0 * 8 + tig + 4) * 72 + n0 * 8 + gid];
                unsigned bs0 = f2tf(bf0), bs1 = f2tf(bf1);
                unsigned br0 = f2tf(bf0 - __uint_as_float(bs0));
                unsigned br1 = f2tf(bf1 - __uint_as_float(bs1));
                mma8(acc[n0], as_, bs0, bs1);
                mma8(acc[n0], ar_, bs0, bs1);
                mma8(acc[n0], as_, br0, br1);
            }
        }
    }

    float* fb = ((outbuf == 0) ? g_feat0 : g_feat1) + (size_t)c_OFF[g] * H;
    int rr0 = row0 + mrow + gid;
    int rr1 = rr0 + 8;
    #pragma unroll
    for (int n0 = 0; n0 < 8; n0++) {
        int cc = n0 * 8 + 2 * tig;
        float b0 = sBias[cc], b1 = sBias[cc + 1];
        if (rr0 < Nd) {
            float2* p = (float2*)(fb + (size_t)rr0 * H + cc);
            *p = make_float2(acc[n0][0] + b0, acc[n0][1] + b1);
        }
        if (rr1 < Nd) {
            float2* p = (float2*)(fb + (size_t)rr1 * H + cc);
            *p = make_float2(acc[n0][2] + b0, acc[n0][3] + b1);
        }
    }
}

// ---------------------------------- pooling -------------------------------------
__global__ void pool_zero() {
    int i = blockIdx.x * blockDim.x + threadIdx.x;
    if (i < NB * 2 * H) g_pool[i] = 0.f;
    if (i < 2 * NB)     g_cnt[i]  = 0.f;
}

// warp per 16 consecutive nodes; batch ids are sorted -> run-length local
// accumulation, one atomic flush per (graph-run, lane).
#define NPW 16
__global__ void pool_kernel(const int* __restrict__ bvar, const int* __restrict__ bcon) {
    int warp = threadIdx.x >> 5, lane = threadIdx.x & 31;
    int gw = blockIdx.x * 8 + warp;
    const int nvw = (N0 + NPW - 1) / NPW;
    const int ncw = (N3 + NPW - 1) / NPW;
    if (gw < nvw) {
        int i0 = gw * NPW, i1 = min(N0, i0 + NPW);
        float a0 = 0.f, a1 = 0.f; float cnt = 0.f;
        int curb = __ldg(&bvar[i0]);
        for (int i = i0; i < i1; i++) {
            int b = __ldg(&bvar[i]);
            if (b != curb) {
                atomicAdd(&g_pool[curb * 128 + lane], a0);
                atomicAdd(&g_pool[curb * 128 + 32 + lane], a1);
                if (lane == 0) atomicAdd(&g_cnt[curb], cnt);
                a0 = a1 = 0.f; cnt = 0.f; curb = b;
            }
            size_t base = (size_t)i * H;
            a0 += fmaxf(g_feat1[base + lane], 0.f);
            a1 += fmaxf(g_feat1[base + 32 + lane], 0.f);
            cnt += 1.f;
        }
        atomicAdd(&g_pool[curb * 128 + lane], a0);
        atomicAdd(&g_pool[curb * 128 + 32 + lane], a1);
        if (lane == 0) atomicAdd(&g_cnt[curb], cnt);
    } else if (gw < nvw + ncw) {
        int gj = gw - nvw;
        const float* xc = g_feat1 + (size_t)(N0 + N1 + N2) * H;
        int i0 = gj * NPW, i1 = min(N3, i0 + NPW);
        float a0 = 0.f, a1 = 0.f; float cnt = 0.f;
        int curb = __ldg(&bcon[i0]);
        for (int i = i0; i < i1; i++) {
            int b = __ldg(&bcon[i]);
            if (b != curb) {
                atomicAdd(&g_pool[curb * 128 + 64 + lane], a0);
                atomicAdd(&g_pool[curb * 128 + 96 + lane], a1);
                if (lane == 0) atomicAdd(&g_cnt[NB + curb], cnt);
                a0 = a1 = 0.f; cnt = 0.f; curb = b;
            }
            size_t base = (size_t)i * H;
            a0 += fmaxf(xc[base + lane], 0.f);
            a1 += fmaxf(xc[base + 32 + lane], 0.f);
            cnt += 1.f;
        }
        atomicAdd(&g_pool[curb * 128 + 64 + lane], a0);
        atomicAdd(&g_pool[curb * 128 + 96 + lane], a1);
        if (lane == 0) atomicAdd(&g_cnt[NB + curb], cnt);
    }
}

__global__ void final_kernel(const float* __restrict__ lw, const float* __restrict__ lb,
                             float* __restrict__ out) {
    int t = threadIdx.x;
    if (t >= 128) return;
    int b = t >> 1, o = t & 1;
    float cv = fmaxf(g_cnt[b], 1.f);
    float cc = fmaxf(g_cnt[NB + b], 1.f);
    float s = lb[o];
    #pragma unroll
    for (int j = 0; j < H; j++) {
        s += (g_pool[b * 128 + j]      / cv) * lw[o * 128 + j];
        s += (g_pool[b * 128 + 64 + j] / cc) * lw[o * 128 + 64 + j];
    }
    out[b * 2 + o] = s;
}

// ---------------------------------- launcher -------------------------------------
extern "C" void kernel_launch(void* const* d_in, const int* in_sizes, int n_in,
                              void* d_out, int out_size) {
    XP xp;
    for (int t = 0; t < 4; t++) xp.x[t] = (const float*)d_in[t];
    const float* Wsrc = (const float*)d_in[4];
    const float* Wdst = (const float*)d_in[5];
    const float* asrc = (const float*)d_in[6];
    const float* adst = (const float*)d_in[7];
    const float* bias = (const float*)d_in[8];
    const float* lw   = (const float*)d_in[9];
    const float* lb   = (const float*)d_in[10];
    EP ep;
    for (int r = 0; r < 9; r++) {
        ep.s[r] = (const int*)d_in[11 + 2 * r];
        ep.d[r] = (const int*)d_in[12 + 2 * r];
    }
    const int* bvar = (const int*)d_in[29];
    const int* bcon = (const int*)d_in[30];

    // CSR build (edges are constant; rebuilt identically every call)
    csr_zero<<<(RTOT * NMAX + 255) / 256, 256>>>();
    csr_hist<<<(ETOT + 255) / 256, 256>>>(ep);
    csr_assign<<<(RTOT * NMAX + 255) / 256, 256>>>();
    csr_fill<<<(ETOT + 255) / 256, 256>>>(ep);
    prep<<<18, 128>>>(Wsrc, asrc, Wdst, adst);

    for (int l = 0; l < 2; l++) {
        const float* Ws_l = Wsrc + (size_t)l * 9 * 4096;
        const float* b_l  = bias + (size_t)l * 9 * 64;
        alpha_all<<<(NTOT + 7) / 8, 256>>>(xp, l, l * 9 * 64);
        gather<<<(NDSUM + 7) / 8, 256>>>(xp, l);
        gemm_out<<<dim3((NMAX + 63) / 64, 4), 128>>>(Ws_l, b_l, l);
    }
    pool_zero<<<(NB * 2 * H + 255) / 256, 256>>>();
    pool_kernel<<<((N0 + NPW - 1) / NPW + (N3 + NPW - 1) / NPW + 7) / 8, 256>>>(bvar, bcon);
    final_kernel<<<1, 128>>>(lw, lb, (float*)d_out);
}

// round 6
// speedup vs baseline: 1.3860x; 1.2576x over previous
#include <cuda_runtime.h>

#define H      64
#define E_PER  300000
#define RTOT   9
#define ETOT   (RTOT * E_PER)
#define NB     64
#define N0     100000
#define N1     20000
#define N2     50000
#define N3     80000
#define NTOT   250000
#define NMAX   100000
#define NDSUM  660000   // sum of Nd over relations

// ---------------- static device scratch ----------------
__device__ float g_feat0[NTOT * H];
__device__ float g_feat1[NTOT * H];
__device__ float g_tmp[(size_t)RTOT * NMAX * H];   // per-relation aggregated src feats
__device__ float g_als[RTOT * NMAX];
__device__ float g_ald[RTOT * NMAX];
__device__ float g_wsv[2 * RTOT * H];              // both layers
__device__ float g_wdv[2 * RTOT * H];
__device__ float g_pool[NB * 2 * H];
__device__ float g_cnt[2 * NB];
// CSR (built once per launch; edges are constant inputs)
__device__ int   g_deg[RTOT * NMAX];
__device__ int   g_off[RTOT * NMAX];
__device__ int   g_cur[RTOT * NMAX];
__device__ int   g_cursor[RTOT];
__device__ int   g_csrc[ETOT];

__constant__ int c_ST[9]  = {0, 0, 0, 2, 3, 1, 2, 3, 3};
__constant__ int c_DT[9]  = {1, 2, 3, 3, 3, 0, 0, 0, 2};
__constant__ int c_NSZ[4] = {N0, N1, N2, N3};
__constant__ int c_OFF[4] = {0, N0, N0 + N1, N0 + N1 + N2};
// cumulative Nd per relation
__constant__ int c_DOFF[10] = {0, 20000, 70000, 150000, 230000, 310000,
                               410000, 510000, 610000, 660000};
// relations targeting type t, -1 padded
__constant__ int c_TB[4][3] = {{5, 6, 7}, {0, -1, -1}, {1, 8, -1}, {2, 3, 4}};

struct XP { const float* x[4]; };
struct EP { const int* s[9]; const int* d[9]; };

// ---------------------------- tf32 helpers ----------------------------
__device__ __forceinline__ unsigned f2tf(float f) {
    unsigned u;
    asm("cvt.rna.tf32.f32 %0, %1;" : "=r"(u) : "f"(f));
    return u;
}
__device__ __forceinline__ void mma8(float* c, const unsigned* a, unsigned b0, unsigned b1) {
    asm volatile(
        "mma.sync.aligned.m16n8k8.row.col.f32.tf32.tf32.f32 "
        "{%0,%1,%2,%3},{%4,%5,%6,%7},{%8,%9},{%0,%1,%2,%3};"
        : "+f"(c[0]), "+f"(c[1]), "+f"(c[2]), "+f"(c[3])
        : "r"(a[0]), "r"(a[1]), "r"(a[2]), "r"(a[3]), "r"(b0), "r"(b1));
}

// ------------------------------- CSR build (once) -------------------------------
__global__ void csr_zero() {
    int i = blockIdx.x * blockDim.x + threadIdx.x;
    if (i < RTOT * NMAX) g_deg[i] = 0;
    if (i < RTOT) g_cursor[i] = 0;
    if (i < NB * 2 * H) g_pool[i] = 0.f;       // fused pool_zero
    if (i < 2 * NB)     g_cnt[i]  = 0.f;
}

__global__ void csr_hist(EP ep) {
    int idx = blockIdx.x * blockDim.x + threadIdx.x;
    if (idx >= ETOT) return;
    int r = idx / E_PER, e = idx - r * E_PER;
    atomicAdd(&g_deg[r * NMAX + __ldg(&ep.d[r][e])], 1);
}

// warp-aggregated offset assignment (list order within a relation is irrelevant)
__global__ void csr_assign() {
    int i = blockIdx.x * blockDim.x + threadIdx.x;
    if (i >= RTOT * NMAX) return;
    int lane = threadIdx.x & 31;
    int r = i / NMAX;                      // NMAX % 32 == 0: warp stays in one r
    int deg = g_deg[i];
    int v = deg;
    #pragma unroll
    for (int o = 1; o < 32; o <<= 1) {
        int t = __shfl_up_sync(0xffffffffu, v, o);
        if (lane >= o) v += t;
    }
    int total = __shfl_sync(0xffffffffu, v, 31);
    int base = 0;
    if (lane == 31) base = atomicAdd(&g_cursor[r], total);
    base = __shfl_sync(0xffffffffu, base, 31);
    g_off[i] = base + v - deg;
    g_cur[i] = 0;                          // fused g_cur zeroing
}

__global__ void csr_fill(EP ep) {
    int idx = blockIdx.x * blockDim.x + threadIdx.x;
    if (idx >= ETOT) return;
    int r = idx / E_PER, e = idx - r * E_PER;
    int d = __ldg(&ep.d[r][e]);
    int pos = atomicAdd(&g_cur[r * NMAX + d], 1);
    g_csrc[r * E_PER + g_off[r * NMAX + d] + pos] = __ldg(&ep.s[r][e]);
}

// ---------------------------------- per-layer -----------------------------------

// both layers: block rl in [0,18): wsv[rl][k] = sum_j Wsrc[rl][k][j]*asrc[rl][j]
__global__ void prep(const float* __restrict__ Ws, const float* __restrict__ as_,
                     const float* __restrict__ Wd, const float* __restrict__ ad_) {
    int rl = blockIdx.x, t = threadIdx.x;
    const float* W; const float* a; float* o; int k;
    if (t < 64) { W = Ws + rl * 4096; a = as_ + rl * 64; o = g_wsv + rl * 64; k = t; }
    else        { W = Wd + rl * 4096; a = ad_ + rl * 64; o = g_wdv + rl * 64; k = t - 64; }
    float s = 0.f;
    #pragma unroll
    for (int j = 0; j < 64; j++) s += W[k * 64 + j] * a[j];
    o[k] = s;
}

// warp per node: attention logits for every (relation, side) of its type
__global__ void alpha_all(XP xp, int use_feat, int wbase) {
    int warp = threadIdx.x >> 5, lane = threadIdx.x & 31;
    int gw = blockIdx.x * 8 + warp;
    if (gw >= NTOT) return;
    int t = (gw < N0) ? 0 : (gw < N0 + N1) ? 1 : (gw < N0 + N1 + N2) ? 2 : 3;
    int li = gw - c_OFF[t];
    const float* x = use_feat ? (g_feat0 + (size_t)c_OFF[t] * H) : xp.x[t];
    float x0 = x[(size_t)li * H + lane];
    float x1 = x[(size_t)li * H + 32 + lane];
    if (use_feat) { x0 = fmaxf(x0, 0.f); x1 = fmaxf(x1, 0.f); }
    #pragma unroll
    for (int r = 0; r < 9; r++) {
        if (c_ST[r] == t) {
            float v = x0 * g_wsv[wbase + r * 64 + lane]
                    + x1 * g_wsv[wbase + r * 64 + 32 + lane];
            #pragma unroll
            for (int o = 16; o; o >>= 1) v += __shfl_xor_sync(0xffffffffu, v, o);
            if (lane == 0) g_als[r * NMAX + li] = v;
        }
        if (c_DT[r] == t) {
            float v = x0 * g_wdv[wbase + r * 64 + lane]
                    + x1 * g_wdv[wbase + r * 64 + 32 + lane];
            #pragma unroll
            for (int o = 16; o; o >>= 1) v += __shfl_xor_sync(0xffffffffu, v, o);
            if (lane == 0) g_ald[r * NMAX + li] = v;
        }
    }
}

// 8-lane group per (relation, dst node): 4 independent dst nodes per warp -> MLP>=4.
// Each lane covers 32B of the 256B feature row (2x float4).
__global__ void __launch_bounds__(256) gather(XP xp, int use_feat) {
    int warp = threadIdx.x >> 5, lane = threadIdx.x & 31;
    int grp = lane >> 3, lg = lane & 7;
    unsigned gmask = 0xFFu << (grp * 8);
    int gw = (blockIdx.x * 8 + warp) * 4 + grp;
    bool active = gw < NDSUM;

    int r = 0;
    if (active) {
        #pragma unroll
        for (int i = 1; i < 9; i++) if (gw >= c_DOFF[i]) r = i;
    }
    int d = active ? (gw - c_DOFF[r]) : 0;
    int st = c_ST[r];
    const float* x = use_feat ? (g_feat0 + (size_t)c_OFF[st] * H) : xp.x[st];
    float ald = active ? __ldg(&g_ald[r * NMAX + d]) : 0.f;
    int beg = active ? __ldg(&g_off[r * NMAX + d]) : 0;
    int deg = active ? __ldg(&g_deg[r * NMAX + d]) : 0;
    const int* sl = g_csrc + r * E_PER + beg;
    const float* als = g_als + r * NMAX;

    float4 a0 = make_float4(0.f, 0.f, 0.f, 0.f);
    float4 a1 = make_float4(0.f, 0.f, 0.f, 0.f);
    float4 b0 = make_float4(0.f, 0.f, 0.f, 0.f);
    float4 b1 = make_float4(0.f, 0.f, 0.f, 0.f);
    float zl = 0.f;

    for (int base = 0; base < deg; base += 8) {
        int n = min(8, deg - base);
        int idx = 0; float p = 0.f;
        if (lg < n) {
            idx = __ldg(&sl[base + lg]);
            float sc = __ldg(&als[idx]) + ald;
            sc = sc > 0.f ? sc : 0.2f * sc;
            p = __expf(sc);
        }
        zl += p;
        int i = 0;
        for (; i + 2 <= n; i += 2) {
            int   s0 = __shfl_sync(gmask, idx, i,     8);
            int   s1 = __shfl_sync(gmask, idx, i + 1, 8);
            float p0 = __shfl_sync(gmask, p,   i,     8);
            float p1 = __shfl_sync(gmask, p,   i + 1, 8);
            const float4* xr0 = (const float4*)(x + (size_t)s0 * H);
            const float4* xr1 = (const float4*)(x + (size_t)s1 * H);
            float4 v0 = xr0[lg * 2], v1 = xr0[lg * 2 + 1];
            float4 w0 = xr1[lg * 2], w1 = xr1[lg * 2 + 1];
            if (use_feat) {
                v0.x = fmaxf(v0.x, 0.f); v0.y = fmaxf(v0.y, 0.f);
                v0.z = fmaxf(v0.z, 0.f); v0.w = fmaxf(v0.w, 0.f);
                v1.x = fmaxf(v1.x, 0.f); v1.y = fmaxf(v1.y, 0.f);
                v1.z = fmaxf(v1.z, 0.f); v1.w = fmaxf(v1.w, 0.f);
                w0.x = fmaxf(w0.x, 0.f); w0.y = fmaxf(w0.y, 0.f);
                w0.z = fmaxf(w0.z, 0.f); w0.w = fmaxf(w0.w, 0.f);
                w1.x = fmaxf(w1.x, 0.f); w1.y = fmaxf(w1.y, 0.f);
                w1.z = fmaxf(w1.z, 0.f); w1.w = fmaxf(w1.w, 0.f);
            }
            a0.x += p0 * v0.x; a0.y += p0 * v0.y; a0.z += p0 * v0.z; a0.w += p0 * v0.w;
            a1.x += p0 * v1.x; a1.y += p0 * v1.y; a1.z += p0 * v1.z; a1.w += p0 * v1.w;
            b0.x += p1 * w0.x; b0.y += p1 * w0.y; b0.z += p1 * w0.z; b0.w += p1 * w0.w;
            b1.x += p1 * w1.x; b1.y += p1 * w1.y; b1.z += p1 * w1.z; b1.w += p1 * w1.w;
        }
        if (i < n) {
            int   s0 = __shfl_sync(gmask, idx, i, 8);
            float p0 = __shfl_sync(gmask, p,   i, 8);
            const float4* xr0 = (const float4*)(x + (size_t)s0 * H);
            float4 v0 = xr0[lg * 2], v1 = xr0[lg * 2 + 1];
            if (use_feat) {
                v0.x = fmaxf(v0.x, 0.f); v0.y = fmaxf(v0.y, 0.f);
                v0.z = fmaxf(v0.z, 0.f); v0.w = fmaxf(v0.w, 0.f);
                v1.x = fmaxf(v1.x, 0.f); v1.y = fmaxf(v1.y, 0.f);
                v1.z = fmaxf(v1.z, 0.f); v1.w = fmaxf(v1.w, 0.f);
            }
            a0.x += p0 * v0.x; a0.y += p0 * v0.y; a0.z += p0 * v0.z; a0.w += p0 * v0.w;
            a1.x += p0 * v1.x; a1.y += p0 * v1.y; a1.z += p0 * v1.z; a1.w += p0 * v1.w;
        }
    }
    // group-wide z reduction (width 8)
    #pragma unroll
    for (int o = 4; o; o >>= 1) zl += __shfl_xor_sync(gmask, zl, o, 8);
    if (active) {
        float inv = __fdividef(1.f, zl + 1e-16f);
        float4* o4 = (float4*)(g_tmp + (size_t)r * NMAX * H + (size_t)d * H);
        o4[lg * 2]     = make_float4((a0.x + b0.x) * inv, (a0.y + b0.y) * inv,
                                     (a0.z + b0.z) * inv, (a0.w + b0.w) * inv);
        o4[lg * 2 + 1] = make_float4((a1.x + b1.x) * inv, (a1.y + b1.y) * inv,
                                     (a1.z + b1.z) * inv, (a1.w + b1.w) * inv);
    }
}

// feat[dtype] = sum_{r->dtype} tmp_r @ Wsrc_r + sum bias_r
__global__ void __launch_bounds__(128) gemm_out(const float* __restrict__ Ws_l,
                                                const float* __restrict__ bias_l,
                                                int outbuf) {
    __shared__ float sA[64 * 72];
    __shared__ float sW[64 * 72];
    __shared__ float sBias[64];
    int g = blockIdx.y;
    int Nd = c_NSZ[g];
    int row0 = blockIdx.x * 64;
    if (row0 >= Nd) return;
    int tid = threadIdx.x;

    if (tid < 64) {
        float s = 0.f;
        #pragma unroll
        for (int i = 0; i < 3; i++) {
            int r = c_TB[g][i];
            if (r >= 0) s += bias_l[r * 64 + tid];
        }
        sBias[tid] = s;
    }

    int warp = tid >> 5, lane = tid & 31;
    int gid = lane >> 2, tig = lane & 3;
    int mrow = warp * 16;

    float acc[8][4];
    #pragma unroll
    for (int n = 0; n < 8; n++)
        #pragma unroll
        for (int j = 0; j < 4; j++) acc[n][j] = 0.f;

    #pragma unroll
    for (int ri = 0; ri < 3; ri++) {
        int r = c_TB[g][ri];
        if (r < 0) break;
        __syncthreads();
        const float4* A4 = (const float4*)(g_tmp + (size_t)r * NMAX * H);
        #pragma unroll
        for (int i = 0; i < 8; i++) {
            int idx = tid + i * 128;
            int rr = idx >> 4, c4 = idx & 15;
            float4 v = make_float4(0.f, 0.f, 0.f, 0.f);
            if (row0 + rr < Nd) v = A4[(size_t)(row0 + rr) * 16 + c4];
            float* dst = sA + rr * 72 + c4 * 4;
            dst[0] = v.x; dst[1] = v.y; dst[2] = v.z; dst[3] = v.w;
        }
        const float4* W4 = (const float4*)(Ws_l + (size_t)r * 4096);
        #pragma unroll
        for (int i = 0; i < 8; i++) {
            int idx = tid + i * 128;
            int rr = idx >> 4, c4 = idx & 15;
            float4 v = W4[idx];
            float* dst = sW + rr * 72 + c4 * 4;
            dst[0] = v.x; dst[1] = v.y; dst[2] = v.z; dst[3] = v.w;
        }
        __syncthreads();

        #pragma unroll
        for (int k0 = 0; k0 < 8; k0++) {
            float af[4];
            af[0] = sA[(mrow + gid)     * 72 + k0 * 8 + tig];
            af[1] = sA[(mrow + gid + 8) * 72 + k0 * 8 + tig];
            af[2] = sA[(mrow + gid)     * 72 + k0 * 8 + tig + 4];
            af[3] = sA[(mrow + gid + 8) * 72 + k0 * 8 + tig + 4];
            unsigned as_[4], ar_[4];
            #pragma unroll
            for (int j = 0; j < 4; j++) {
                as_[j] = f2tf(af[j]);
                ar_[j] = f2tf(af[j] - __uint_as_float(as_[j]));
            }
            #pragma unroll
            for (int n0 = 0; n0 < 8; n0++) {
                float bf0 = sW[(k0 * 8 + tig)     * 72 + n0 * 8 + gid];
                float bf1 = sW[(k0 * 8 + tig + 4) * 72 + n0 * 8 + gid];
                unsigned bs0 = f2tf(bf0), bs1 = f2tf(bf1);
                unsigned br0 = f2tf(bf0 - __uint_as_float(bs0));
                unsigned br1 = f2tf(bf1 - __uint_as_float(bs1));
                mma8(acc[n0], as_, bs0, bs1);
                mma8(acc[n0], ar_, bs0, bs1);
                mma8(acc[n0], as_, br0, br1);
            }
        }
    }

    float* fb = ((outbuf == 0) ? g_feat0 : g_feat1) + (size_t)c_OFF[g] * H;
    int rr0 = row0 + mrow + gid;
    int rr1 = rr0 + 8;
    #pragma unroll
    for (int n0 = 0; n0 < 8; n0++) {
        int cc = n0 * 8 + 2 * tig;
        float b0 = sBias[cc], b1 = sBias[cc + 1];
        if (rr0 < Nd) {
            float2* p = (float2*)(fb + (size_t)rr0 * H + cc);
            *p = make_float2(acc[n0][0] + b0, acc[n0][1] + b1);
        }
        if (rr1 < Nd) {
            float2* p = (float2*)(fb + (size_t)rr1 * H + cc);
            *p = make_float2(acc[n0][2] + b0, acc[n0][3] + b1);
        }
    }
}

// ---------------------------------- pooling -------------------------------------
// warp per 16 consecutive nodes; batch ids are sorted -> run-length local
// accumulation, one atomic flush per (graph-run, lane).
#define NPW 16
__global__ void pool_kernel(const int* __restrict__ bvar, const int* __restrict__ bcon) {
    int warp = threadIdx.x >> 5, lane = threadIdx.x & 31;
    int gw = blockIdx.x * 8 + warp;
    const int nvw = (N0 + NPW - 1) / NPW;
    const int ncw = (N3 + NPW - 1) / NPW;
    if (gw < nvw) {
        int i0 = gw * NPW, i1 = min(N0, i0 + NPW);
        float a0 = 0.f, a1 = 0.f; float cnt = 0.f;
        int curb = __ldg(&bvar[i0]);
        for (int i = i0; i < i1; i++) {
            int b = __ldg(&bvar[i]);
            if (b != curb) {
                atomicAdd(&g_pool[curb * 128 + lane], a0);
                atomicAdd(&g_pool[curb * 128 + 32 + lane], a1);
                if (lane == 0) atomicAdd(&g_cnt[curb], cnt);
                a0 = a1 = 0.f; cnt = 0.f; curb = b;
            }
            size_t base = (size_t)i * H;
            a0 += fmaxf(g_feat1[base + lane], 0.f);
            a1 += fmaxf(g_feat1[base + 32 + lane], 0.f);
            cnt += 1.f;
        }
        atomicAdd(&g_pool[curb * 128 + lane], a0);
        atomicAdd(&g_pool[curb * 128 + 32 + lane], a1);
        if (lane == 0) atomicAdd(&g_cnt[curb], cnt);
    } else if (gw < nvw + ncw) {
        int gj = gw - nvw;
        const float* xc = g_feat1 + (size_t)(N0 + N1 + N2) * H;
        int i0 = gj * NPW, i1 = min(N3, i0 + NPW);
        float a0 = 0.f, a1 = 0.f; float cnt = 0.f;
        int curb = __ldg(&bcon[i0]);
        for (int i = i0; i < i1; i++) {
            int b = __ldg(&bcon[i]);
            if (b != curb) {
                atomicAdd(&g_pool[curb * 128 + 64 + lane], a0);
                atomicAdd(&g_pool[curb * 128 + 96 + lane], a1);
                if (lane == 0) atomicAdd(&g_cnt[NB + curb], cnt);
                a0 = a1 = 0.f; cnt = 0.f; curb = b;
            }
            size_t base = (size_t)i * H;
            a0 += fmaxf(xc[base + lane], 0.f);
            a1 += fmaxf(xc[base + 32 + lane], 0.f);
            cnt += 1.f;
        }
        atomicAdd(&g_pool[curb * 128 + 64 + lane], a0);
        atomicAdd(&g_pool[curb * 128 + 96 + lane], a1);
        if (lane == 0) atomicAdd(&g_cnt[NB + curb], cnt);
    }
}

__global__ void final_kernel(const float* __restrict__ lw, const float* __restrict__ lb,
                             float* __restrict__ out) {
    int t = threadIdx.x;
    if (t >= 128) return;
    int b = t >> 1, o = t & 1;
    float cv = fmaxf(g_cnt[b], 1.f);
    float cc = fmaxf(g_cnt[NB + b], 1.f);
    float s = lb[o];
    #pragma unroll
    for (int j = 0; j < H; j++) {
        s += (g_pool[b * 128 + j]      / cv) * lw[o * 128 + j];
        s += (g_pool[b * 128 + 64 + j] / cc) * lw[o * 128 + 64 + j];
    }
    out[b * 2 + o] = s;
}

// ---------------------------------- launcher -------------------------------------
extern "C" void kernel_launch(void* const* d_in, const int* in_sizes, int n_in,
                              void* d_out, int out_size) {
    XP xp;
    for (int t = 0; t < 4; t++) xp.x[t] = (const float*)d_in[t];
    const float* Wsrc = (const float*)d_in[4];
    const float* Wdst = (const float*)d_in[5];
    const float* asrc = (const float*)d_in[6];
    const float* adst = (const float*)d_in[7];
    const float* bias = (const float*)d_in[8];
    const float* lw   = (const float*)d_in[9];
    const float* lb   = (const float*)d_in[10];
    EP ep;
    for (int r = 0; r < 9; r++) {
        ep.s[r] = (const int*)d_in[11 + 2 * r];
        ep.d[r] = (const int*)d_in[12 + 2 * r];
    }
    const int* bvar = (const int*)d_in[29];
    const int* bcon = (const int*)d_in[30];

    // CSR build (edges are constant; rebuilt identically every call)
    csr_zero<<<(RTOT * NMAX + 255) / 256, 256>>>();
    csr_hist<<<(ETOT + 255) / 256, 256>>>(ep);
    csr_assign<<<(RTOT * NMAX + 255) / 256, 256>>>();
    csr_fill<<<(ETOT + 255) / 256, 256>>>(ep);
    prep<<<18, 128>>>(Wsrc, asrc, Wdst, adst);

    for (int l = 0; l < 2; l++) {
        const float* Ws_l = Wsrc + (size_t)l * 9 * 4096;
        const float* b_l  = bias + (size_t)l * 9 * 64;
        alpha_all<<<(NTOT + 7) / 8, 256>>>(xp, l, l * 9 * 64);
        gather<<<(NDSUM / 4 + 7) / 8, 256>>>(xp, l);
        gemm_out<<<dim3((NMAX + 63) / 64, 4), 128>>>(Ws_l, b_l, l);
    }
    pool_kernel<<<((N0 + NPW - 1) / NPW + (N3 + NPW - 1) / NPW + 7) / 8, 256>>>(bvar, bcon);
    final_kernel<<<1, 128>>>(lw, lb, (float*)d_out);
}

// round 7
// speedup vs baseline: 1.4121x; 1.0188x over previous
#include <cuda_runtime.h>

#define H      64
#define E_PER  300000
#define RTOT   9
#define ETOT   (RTOT * E_PER)
#define NB     64
#define N0     100000
#define N1     20000
#define N2     50000
#define N3     80000
#define NTOT   250000
#define NMAX   100000
#define NDSUM  660000   // sum of Nd over relations

// ---------------- static device scratch ----------------
__device__ float g_feat0[NTOT * H];
__device__ float g_feat1[NTOT * H];
__device__ float g_als[RTOT * NMAX];
__device__ float g_ald[RTOT * NMAX];
__device__ float g_wsv[2 * RTOT * H];
__device__ float g_wdv[2 * RTOT * H];
__device__ float g_pool[NB * 2 * H];
__device__ float g_cnt[2 * NB];
// compact CSR: entry index = c_DOFF[r] + d ; offsets are global into g_csrc
__device__ int   g_deg[NDSUM];
__device__ int   g_off[NDSUM];
__device__ int   g_cur[NDSUM];
__device__ int   g_cursor[1];
__device__ int   g_csrc[ETOT];

__constant__ int c_ST[9]  = {0, 0, 0, 2, 3, 1, 2, 3, 3};
__constant__ int c_NSZ[4] = {N0, N1, N2, N3};
__constant__ int c_OFF[4] = {0, N0, N0 + N1, N0 + N1 + N2};
__constant__ int c_DOFF[10] = {0, 20000, 70000, 150000, 230000, 310000,
                               410000, 510000, 610000, 660000};
// relations targeting type t, -1 padded
__constant__ int c_TB[4][3] = {{5, 6, 7}, {0, -1, -1}, {1, 8, -1}, {2, 3, 4}};
// cumulative 32-row tile counts per dst type
__constant__ int c_TILE0[5] = {0, 3125, 3750, 5313, 7813};

struct XP { const float* x[4]; };
struct EP { const int* s[9]; const int* d[9]; };

// ---------------------------- tf32 helpers ----------------------------
__device__ __forceinline__ unsigned f2tf(float f) {
    unsigned u;
    asm("cvt.rna.tf32.f32 %0, %1;" : "=r"(u) : "f"(f));
    return u;
}
__device__ __forceinline__ void mma8(float* c, const unsigned* a, unsigned b0, unsigned b1) {
    asm volatile(
        "mma.sync.aligned.m16n8k8.row.col.f32.tf32.tf32.f32 "
        "{%0,%1,%2,%3},{%4,%5,%6,%7},{%8,%9},{%0,%1,%2,%3};"
        : "+f"(c[0]), "+f"(c[1]), "+f"(c[2]), "+f"(c[3])
        : "r"(a[0]), "r"(a[1]), "r"(a[2]), "r"(a[3]), "r"(b0), "r"(b1));
}

// ------------------------------- CSR build (once) -------------------------------
__global__ void csr_zero() {
    int i = blockIdx.x * blockDim.x + threadIdx.x;
    if (i < NDSUM) g_deg[i] = 0;
    if (i == 0)    g_cursor[0] = 0;
    if (i < NB * 2 * H) g_pool[i] = 0.f;       // fused pool_zero
    if (i < 2 * NB)     g_cnt[i]  = 0.f;
}

__global__ void csr_hist(EP ep) {
    int idx = blockIdx.x * blockDim.x + threadIdx.x;
    if (idx >= ETOT) return;
    int r = idx / E_PER, e = idx - r * E_PER;
    atomicAdd(&g_deg[c_DOFF[r] + __ldg(&ep.d[r][e])], 1);
}

// block-aggregated global offset assignment (one cursor; list order irrelevant)
__global__ void csr_assign() {
    int i = blockIdx.x * 256 + threadIdx.x;
    int lane = threadIdx.x & 31, w = threadIdx.x >> 5;
    __shared__ int sm[8];
    int deg = (i < NDSUM) ? g_deg[i] : 0;
    int v = deg;
    #pragma unroll
    for (int o = 1; o < 32; o <<= 1) {
        int t = __shfl_up_sync(0xffffffffu, v, o);
        if (lane >= o) v += t;
    }
    if (lane == 31) sm[w] = v;
    __syncthreads();
    if (threadIdx.x == 0) {
        int tmp[8];
        int s = 0;
        #pragma unroll
        for (int k = 0; k < 8; k++) { tmp[k] = s; s += sm[k]; }
        int b = atomicAdd(&g_cursor[0], s);
        #pragma unroll
        for (int k = 0; k < 8; k++) sm[k] = tmp[k] + b;
    }
    __syncthreads();
    if (i < NDSUM) { g_off[i] = sm[w] + v - deg; g_cur[i] = 0; }
}

__global__ void csr_fill(EP ep) {
    int idx = blockIdx.x * blockDim.x + threadIdx.x;
    if (idx >= ETOT) return;
    int r = idx / E_PER, e = idx - r * E_PER;
    int gi = c_DOFF[r] + __ldg(&ep.d[r][e]);
    int pos = atomicAdd(&g_cur[gi], 1);
    g_csrc[g_off[gi] + pos] = __ldg(&ep.s[r][e]);
}

// ---------------------------------- per-layer -----------------------------------

// both layers: block rl in [0,18): wsv[rl][k] = sum_j Wsrc[rl][k][j]*asrc[rl][j]
__global__ void prep(const float* __restrict__ Ws, const float* __restrict__ as_,
                     const float* __restrict__ Wd, const float* __restrict__ ad_) {
    int rl = blockIdx.x, t = threadIdx.x;
    const float* W; const float* a; float* o; int k;
    if (t < 64) { W = Ws + rl * 4096; a = as_ + rl * 64; o = g_wsv + rl * 64; k = t; }
    else        { W = Wd + rl * 4096; a = ad_ + rl * 64; o = g_wdv + rl * 64; k = t - 64; }
    float s = 0.f;
    #pragma unroll
    for (int j = 0; j < 64; j++) s += W[k * 64 + j] * a[j];
    o[k] = s;
}

// warp per node: attention logits for every (relation, side) of its type
__global__ void alpha_all(XP xp, int use_feat, int wbase) {
    int warp = threadIdx.x >> 5, lane = threadIdx.x & 31;
    int gw = blockIdx.x * 8 + warp;
    if (gw >= NTOT) return;
    int t = (gw < N0) ? 0 : (gw < N0 + N1) ? 1 : (gw < N0 + N1 + N2) ? 2 : 3;
    int li = gw - c_OFF[t];
    const float* x = use_feat ? (g_feat0 + (size_t)c_OFF[t] * H) : xp.x[t];
    float x0 = x[(size_t)li * H + lane];
    float x1 = x[(size_t)li * H + 32 + lane];
    if (use_feat) { x0 = fmaxf(x0, 0.f); x1 = fmaxf(x1, 0.f); }
    #pragma unroll
    for (int r = 0; r < 9; r++) {
        if (c_ST[r] == t) {
            float v = x0 * g_wsv[wbase + r * 64 + lane]
                    + x1 * g_wsv[wbase + r * 64 + 32 + lane];
            #pragma unroll
            for (int o = 16; o; o >>= 1) v += __shfl_xor_sync(0xffffffffu, v, o);
            if (lane == 0) g_als[r * NMAX + li] = v;
        }
        int dt = (r < 3) ? (r + 1) : (r == 3 || r == 4) ? 3 : (r < 8) ? 0 : 2;
        if (dt == t) {
            float v = x0 * g_wdv[wbase + r * 64 + lane]
                    + x1 * g_wdv[wbase + r * 64 + 32 + lane];
            #pragma unroll
            for (int o = 16; o; o >>= 1) v += __shfl_xor_sync(0xffffffffu, v, o);
            if (lane == 0) g_ald[r * NMAX + li] = v;
        }
    }
}

// Fused gather + GEMM per dst-type tile of 32 rows.
// Per relation r targeting this type: gather softmax-weighted sum of x_act[src]
// into sG (8-lane group per node, 4 nodes per warp), then 3xTF32 MMA with
// register accumulation across relations. Epilogue adds summed bias.
__global__ void __launch_bounds__(256) fused(XP xp, const float* __restrict__ Ws_l,
                                             const float* __restrict__ bias_l,
                                             int use_feat, int outbuf) {
    __shared__ float sG[32 * 72];
    __shared__ float sW[64 * 72];
    __shared__ float sBias[64];
    int bx = blockIdx.x;
    int t = 0;
    #pragma unroll
    for (int i = 1; i < 4; i++) if (bx >= c_TILE0[i]) t = i;
    int row0 = (bx - c_TILE0[t]) * 32;
    int Nd = c_NSZ[t];
    int tid = threadIdx.x, warp = tid >> 5, lane = tid & 31;
    int grp = lane >> 3, lg = lane & 7;
    unsigned gmask = 0xFFu << (grp * 8);
    int nl = warp * 4 + grp;           // local node 0..31
    int d = row0 + nl;
    bool act = d < Nd;

    if (tid < 64) {
        float s = 0.f;
        #pragma unroll
        for (int i = 0; i < 3; i++) {
            int r = c_TB[t][i];
            if (r >= 0) s += bias_l[r * 64 + tid];
        }
        sBias[tid] = s;
    }

    // MMA layout: warps 0..3. warp&1 selects 16-row half, warp>>1 selects 32-col half
    int mrow = (warp & 1) * 16;
    int nh = warp >> 1;
    int gid = lane >> 2, tig = lane & 3;
    float acc[4][4];
    #pragma unroll
    for (int n = 0; n < 4; n++)
        #pragma unroll
        for (int j = 0; j < 4; j++) acc[n][j] = 0.f;

    #pragma unroll
    for (int ri = 0; ri < 3; ri++) {
        int r = c_TB[t][ri];
        if (r < 0) break;
        int st = c_ST[r];
        const float* x = use_feat ? (g_feat0 + (size_t)c_OFF[st] * H) : xp.x[st];
        __syncthreads();               // previous MMA done with sG/sW

        const float4* W4 = (const float4*)(Ws_l + (size_t)r * 4096);
        #pragma unroll
        for (int i = 0; i < 4; i++) {
            int idx = tid + i * 256;
            int rr = idx >> 4, c4 = idx & 15;
            float4 v = W4[idx];
            float* dst = sW + rr * 72 + c4 * 4;
            dst[0] = v.x; dst[1] = v.y; dst[2] = v.z; dst[3] = v.w;
        }

        // ---- gather this node's neighbors for relation r ----
        float ald = 0.f; int beg = 0, deg = 0;
        if (act) {
            int gi = c_DOFF[r] + d;
            ald = __ldg(&g_ald[(size_t)r * NMAX + d]);
            beg = __ldg(&g_off[gi]);
            deg = __ldg(&g_deg[gi]);
        }
        const int* sl = g_csrc + beg;
        const float* als = g_als + (size_t)r * NMAX;

        float4 a0 = make_float4(0.f, 0.f, 0.f, 0.f);
        float4 a1 = make_float4(0.f, 0.f, 0.f, 0.f);
        float4 b0 = make_float4(0.f, 0.f, 0.f, 0.f);
        float4 b1 = make_float4(0.f, 0.f, 0.f, 0.f);
        float zl = 0.f;
        for (int base = 0; base < deg; base += 8) {
            int n = min(8, deg - base);
            int sidx = 0; float p = 0.f;
            if (lg < n) {
                sidx = __ldg(&sl[base + lg]);
                float sc = __ldg(&als[sidx]) + ald;
                sc = sc > 0.f ? sc : 0.2f * sc;
                p = __expf(sc);
            }
            zl += p;
            int i = 0;
            for (; i + 2 <= n; i += 2) {
                int   s0 = __shfl_sync(gmask, sidx, i,     8);
                int   s1 = __shfl_sync(gmask, sidx, i + 1, 8);
                float p0 = __shfl_sync(gmask, p,    i,     8);
                float p1 = __shfl_sync(gmask, p,    i + 1, 8);
                const float4* xr0 = (const float4*)(x + (size_t)s0 * H);
                const float4* xr1 = (const float4*)(x + (size_t)s1 * H);
                float4 v0 = xr0[lg * 2], v1 = xr0[lg * 2 + 1];
                float4 w0 = xr1[lg * 2], w1 = xr1[lg * 2 + 1];
                if (use_feat) {
                    v0.x = fmaxf(v0.x, 0.f); v0.y = fmaxf(v0.y, 0.f);
                    v0.z = fmaxf(v0.z, 0.f); v0.w = fmaxf(v0.w, 0.f);
                    v1.x = fmaxf(v1.x, 0.f); v1.y = fmaxf(v1.y, 0.f);
                    v1.z = fmaxf(v1.z, 0.f); v1.w = fmaxf(v1.w, 0.f);
                    w0.x = fmaxf(w0.x, 0.f); w0.y = fmaxf(w0.y, 0.f);
                    w0.z = fmaxf(w0.z, 0.f); w0.w = fmaxf(w0.w, 0.f);
                    w1.x = fmaxf(w1.x, 0.f); w1.y = fmaxf(w1.y, 0.f);
                    w1.z = fmaxf(w1.z, 0.f); w1.w = fmaxf(w1.w, 0.f);
                }
                a0.x += p0 * v0.x; a0.y += p0 * v0.y; a0.z += p0 * v0.z; a0.w += p0 * v0.w;
                a1.x += p0 * v1.x; a1.y += p0 * v1.y; a1.z += p0 * v1.z; a1.w += p0 * v1.w;
                b0.x += p1 * w0.x; b0.y += p1 * w0.y; b0.z += p1 * w0.z; b0.w += p1 * w0.w;
                b1.x += p1 * w1.x; b1.y += p1 * w1.y; b1.z += p1 * w1.z; b1.w += p1 * w1.w;
            }
            if (i < n) {
                int   s0 = __shfl_sync(gmask, sidx, i, 8);
                float p0 = __shfl_sync(gmask, p,    i, 8);
                const float4* xr0 = (const float4*)(x + (size_t)s0 * H);
                float4 v0 = xr0[lg * 2], v1 = xr0[lg * 2 + 1];
                if (use_feat) {
                    v0.x = fmaxf(v0.x, 0.f); v0.y = fmaxf(v0.y, 0.f);
                    v0.z = fmaxf(v0.z, 0.f); v0.w = fmaxf(v0.w, 0.f);
                    v1.x = fmaxf(v1.x, 0.f); v1.y = fmaxf(v1.y, 0.f);
                    v1.z = fmaxf(v1.z, 0.f); v1.w = fmaxf(v1.w, 0.f);
                }
                a0.x += p0 * v0.x; a0.y += p0 * v0.y; a0.z += p0 * v0.z; a0.w += p0 * v0.w;
                a1.x += p0 * v1.x; a1.y += p0 * v1.y; a1.z += p0 * v1.z; a1.w += p0 * v1.w;
            }
        }
        #pragma unroll
        for (int o = 4; o; o >>= 1) zl += __shfl_xor_sync(gmask, zl, o, 8);
        float inv = act ? __fdividef(1.f, zl + 1e-16f) : 0.f;
        float* gr = sG + nl * 72 + lg * 8;
        ((float4*)gr)[0] = make_float4((a0.x + b0.x) * inv, (a0.y + b0.y) * inv,
                                       (a0.z + b0.z) * inv, (a0.w + b0.w) * inv);
        ((float4*)gr)[1] = make_float4((a1.x + b1.x) * inv, (a1.y + b1.y) * inv,
                                       (a1.z + b1.z) * inv, (a1.w + b1.w) * inv);
        __syncthreads();

        // ---- 3xTF32 MMA: acc += sG @ W_r ----
        if (warp < 4) {
            #pragma unroll
            for (int k0 = 0; k0 < 8; k0++) {
                float af[4];
                af[0] = sG[(mrow + gid)     * 72 + k0 * 8 + tig];
                af[1] = sG[(mrow + gid + 8) * 72 + k0 * 8 + tig];
                af[2] = sG[(mrow + gid)     * 72 + k0 * 8 + tig + 4];
                af[3] = sG[(mrow + gid + 8) * 72 + k0 * 8 + tig + 4];
                unsigned as_[4], ar_[4];
                #pragma unroll
                for (int j = 0; j < 4; j++) {
                    as_[j] = f2tf(af[j]);
                    ar_[j] = f2tf(af[j] - __uint_as_float(as_[j]));
                }
                #pragma unroll
                for (int n0 = 0; n0 < 4; n0++) {
                    int nc = (nh * 4 + n0) * 8 + gid;
                    float bf0 = sW[(k0 * 8 + tig)     * 72 + nc];
                    float bf1 = sW[(k0 * 8 + tig + 4) * 72 + nc];
                    unsigned bs0 = f2tf(bf0), bs1 = f2tf(bf1);
                    unsigned br0 = f2tf(bf0 - __uint_as_float(bs0));
                    unsigned br1 = f2tf(bf1 - __uint_as_float(bs1));
                    mma8(acc[n0], as_, bs0, bs1);
                    mma8(acc[n0], ar_, bs0, bs1);
                    mma8(acc[n0], as_, br0, br1);
                }
            }
        }
    }

    if (warp < 4) {
        float* fb = ((outbuf == 0) ? g_feat0 : g_feat1) + (size_t)c_OFF[t] * H;
        int rr0 = row0 + mrow + gid;
        int rr1 = rr0 + 8;
        #pragma unroll
        for (int n0 = 0; n0 < 4; n0++) {
            int cc = (nh * 4 + n0) * 8 + 2 * tig;
            float bv0 = sBias[cc], bv1 = sBias[cc + 1];
            if (rr0 < Nd) {
                float2* p = (float2*)(fb + (size_t)rr0 * H + cc);
                *p = make_float2(acc[n0][0] + bv0, acc[n0][1] + bv1);
            }
            if (rr1 < Nd) {
                float2* p = (float2*)(fb + (size_t)rr1 * H + cc);
                *p = make_float2(acc[n0][2] + bv0, acc[n0][3] + bv1);
            }
        }
    }
}

// ---------------------------------- pooling -------------------------------------
#define NPW 16
__global__ void pool_kernel(const int* __restrict__ bvar, const int* __restrict__ bcon) {
    int warp = threadIdx.x >> 5, lane = threadIdx.x & 31;
    int gw = blockIdx.x * 8 + warp;
    const int nvw = (N0 + NPW - 1) / NPW;
    const int ncw = (N3 + NPW - 1) / NPW;
    if (gw < nvw) {
        int i0 = gw * NPW, i1 = min(N0, i0 + NPW);
        float a0 = 0.f, a1 = 0.f; float cnt = 0.f;
        int curb = __ldg(&bvar[i0]);
        for (int i = i0; i < i1; i++) {
            int b = __ldg(&bvar[i]);
            if (b != curb) {
                atomicAdd(&g_pool[curb * 128 + lane], a0);
                atomicAdd(&g_pool[curb * 128 + 32 + lane], a1);
                if (lane == 0) atomicAdd(&g_cnt[curb], cnt);
                a0 = a1 = 0.f; cnt = 0.f; curb = b;
            }
            size_t base = (size_t)i * H;
            a0 += fmaxf(g_feat1[base + lane], 0.f);
            a1 += fmaxf(g_feat1[base + 32 + lane], 0.f);
            cnt += 1.f;
        }
        atomicAdd(&g_pool[curb * 128 + lane], a0);
        atomicAdd(&g_pool[curb * 128 + 32 + lane], a1);
        if (lane == 0) atomicAdd(&g_cnt[curb], cnt);
    } else if (gw < nvw + ncw) {
        int gj = gw - nvw;
        const float* xc = g_feat1 + (size_t)(N0 + N1 + N2) * H;
        int i0 = gj * NPW, i1 = min(N3, i0 + NPW);
        float a0 = 0.f, a1 = 0.f; float cnt = 0.f;
        int curb = __ldg(&bcon[i0]);
        for (int i = i0; i < i1; i++) {
            int b = __ldg(&bcon[i]);
            if (b != curb) {
                atomicAdd(&g_pool[curb * 128 + 64 + lane], a0);
                atomicAdd(&g_pool[curb * 128 + 96 + lane], a1);
                if (lane == 0) atomicAdd(&g_cnt[NB + curb], cnt);
                a0 = a1 = 0.f; cnt = 0.f; curb = b;
            }
            size_t base = (size_t)i * H;
            a0 += fmaxf(xc[base + lane], 0.f);
            a1 += fmaxf(xc[base + 32 + lane], 0.f);
            cnt += 1.f;
        }
        atomicAdd(&g_pool[curb * 128 + 64 + lane], a0);
        atomicAdd(&g_pool[curb * 128 + 96 + lane], a1);
        if (lane == 0) atomicAdd(&g_cnt[NB + curb], cnt);
    }
}

__global__ void final_kernel(const float* __restrict__ lw, const float* __restrict__ lb,
                             float* __restrict__ out) {
    int t = threadIdx.x;
    if (t >= 128) return;
    int b = t >> 1, o = t & 1;
    float cv = fmaxf(g_cnt[b], 1.f);
    float cc = fmaxf(g_cnt[NB + b], 1.f);
    float s = lb[o];
    #pragma unroll
    for (int j = 0; j < H; j++) {
        s += (g_pool[b * 128 + j]      / cv) * lw[o * 128 + j];
        s += (g_pool[b * 128 + 64 + j] / cc) * lw[o * 128 + 64 + j];
    }
    out[b * 2 + o] = s;
}

// ---------------------------------- launcher -------------------------------------
extern "C" void kernel_launch(void* const* d_in, const int* in_sizes, int n_in,
                              void* d_out, int out_size) {
    XP xp;
    for (int t = 0; t < 4; t++) xp.x[t] = (const float*)d_in[t];
    const float* Wsrc = (const float*)d_in[4];
    const float* Wdst = (const float*)d_in[5];
    const float* asrc = (const float*)d_in[6];
    const float* adst = (const float*)d_in[7];
    const float* bias = (const float*)d_in[8];
    const float* lw   = (const float*)d_in[9];
    const float* lb   = (const float*)d_in[10];
    EP ep;
    for (int r = 0; r < 9; r++) {
        ep.s[r] = (const int*)d_in[11 + 2 * r];
        ep.d[r] = (const int*)d_in[12 + 2 * r];
    }
    const int* bvar = (const int*)d_in[29];
    const int* bcon = (const int*)d_in[30];

    // CSR build (edges are constant; rebuilt identically every call)
    csr_zero<<<(NDSUM + 255) / 256, 256>>>();
    csr_hist<<<(ETOT + 255) / 256, 256>>>(ep);
    csr_assign<<<(NDSUM + 255) / 256, 256>>>();
    csr_fill<<<(ETOT + 255) / 256, 256>>>(ep);
    prep<<<18, 128>>>(Wsrc, asrc, Wdst, adst);

    for (int l = 0; l < 2; l++) {
        const float* Ws_l = Wsrc + (size_t)l * 9 * 4096;
        const float* b_l  = bias + (size_t)l * 9 * 64;
        alpha_all<<<(NTOT + 7) / 8, 256>>>(xp, l, l * 9 * 64);
        fused<<<7813, 256>>>(xp, Ws_l, b_l, l, l);
    }
    pool_kernel<<<((N0 + NPW - 1) / NPW + (N3 + NPW - 1) / NPW + 7) / 8, 256>>>(bvar, bcon);
    final_kernel<<<1, 128>>>(lw, lb, (float*)d_out);
}

// round 8
// speedup vs baseline: 1.4489x; 1.0261x over previous
#include <cuda_runtime.h>
#include <cuda_fp16.h>

#define H      64
#define E_PER  300000
#define RTOT   9
#define ETOT   (RTOT * E_PER)
#define NB     64
#define N0     100000
#define N1     20000
#define N2     50000
#define N3     80000
#define NTOT   250000
#define NMAX   100000
#define NDSUM  660000   // sum of Nd over relations

// ---------------- static device scratch ----------------
__device__ float   g_feat0[NTOT * H];
__device__ float   g_feat1[NTOT * H];
__device__ __half2 g_xh[(size_t)NTOT * 32];   // fp16 activated features (per layer)
__device__ float   g_als[RTOT * NMAX];
__device__ float   g_ald[RTOT * NMAX];
__device__ float   g_wsv[2 * RTOT * H];
__device__ float   g_wdv[2 * RTOT * H];
__device__ float   g_pool[NB * 2 * H];
__device__ float   g_cnt[2 * NB];
// compact CSR: entry index = c_DOFF[r] + d ; offsets are global into g_csrc
__device__ int     g_deg[NDSUM];
__device__ int     g_off[NDSUM];
__device__ int     g_cursor[1];
__device__ int     g_csrc[ETOT];
__device__ int     g_epos[ETOT];              // per-edge slot from hist pass

__constant__ int c_ST[9]  = {0, 0, 0, 2, 3, 1, 2, 3, 3};
__constant__ int c_NSZ[4] = {N0, N1, N2, N3};
__constant__ int c_OFF[4] = {0, N0, N0 + N1, N0 + N1 + N2};
__constant__ int c_DOFF[10] = {0, 20000, 70000, 150000, 230000, 310000,
                               410000, 510000, 610000, 660000};
// relations targeting type t, -1 padded
__constant__ int c_TB[4][3] = {{5, 6, 7}, {0, -1, -1}, {1, 8, -1}, {2, 3, 4}};
// cumulative 32-row tile counts per dst type
__constant__ int c_TILE0[5] = {0, 3125, 3750, 5313, 7813};

struct XP { const float* x[4]; };
struct EP { const int* s[9]; const int* d[9]; };

// ---------------------------- tf32 helpers ----------------------------
__device__ __forceinline__ unsigned f2tf(float f) {
    unsigned u;
    asm("cvt.rna.tf32.f32 %0, %1;" : "=r"(u) : "f"(f));
    return u;
}
__device__ __forceinline__ void mma8(float* c, const unsigned* a, unsigned b0, unsigned b1) {
    asm volatile(
        "mma.sync.aligned.m16n8k8.row.col.f32.tf32.tf32.f32 "
        "{%0,%1,%2,%3},{%4,%5,%6,%7},{%8,%9},{%0,%1,%2,%3};"
        : "+f"(c[0]), "+f"(c[1]), "+f"(c[2]), "+f"(c[3])
        : "r"(a[0]), "r"(a[1]), "r"(a[2]), "r"(a[3]), "r"(b0), "r"(b1));
}

// fp16 row chunk (8 halves) weighted-accumulate into 8 fp32 accumulators
__device__ __forceinline__ void acc_h8(float* acc, float4 q, float pw) {
    __half2* h = (__half2*)&q;
    #pragma unroll
    for (int j = 0; j < 4; j++) {
        float2 f = __half22float2(h[j]);
        acc[2 * j]     += pw * f.x;
        acc[2 * j + 1] += pw * f.y;
    }
}

// ------------------------------- CSR build (once) -------------------------------
__global__ void csr_zero() {
    int i = blockIdx.x * blockDim.x + threadIdx.x;
    if (i < NDSUM) g_deg[i] = 0;
    if (i == 0)    g_cursor[0] = 0;
    if (i < NB * 2 * H) g_pool[i] = 0.f;       // fused pool_zero
    if (i < 2 * NB)     g_cnt[i]  = 0.f;
}

// histogram; also records each edge's slot within its dst list
__global__ void csr_hist(EP ep) {
    int idx = blockIdx.x * blockDim.x + threadIdx.x;
    if (idx >= ETOT) return;
    int r = idx / E_PER, e = idx - r * E_PER;
    int gi = c_DOFF[r] + __ldg(&ep.d[r][e]);
    g_epos[idx] = atomicAdd(&g_deg[gi], 1);
}

// block-aggregated global offset assignment (one cursor; list order irrelevant)
__global__ void csr_assign() {
    int i = blockIdx.x * 256 + threadIdx.x;
    int lane = threadIdx.x & 31, w = threadIdx.x >> 5;
    __shared__ int sm[8];
    int deg = (i < NDSUM) ? g_deg[i] : 0;
    int v = deg;
    #pragma unroll
    for (int o = 1; o < 32; o <<= 1) {
        int t = __shfl_up_sync(0xffffffffu, v, o);
        if (lane >= o) v += t;
    }
    if (lane == 31) sm[w] = v;
    __syncthreads();
    if (threadIdx.x == 0) {
        int tmp[8];
        int s = 0;
        #pragma unroll
        for (int k = 0; k < 8; k++) { tmp[k] = s; s += sm[k]; }
        int b = atomicAdd(&g_cursor[0], s);
        #pragma unroll
        for (int k = 0; k < 8; k++) sm[k] = tmp[k] + b;
    }
    __syncthreads();
    if (i < NDSUM) g_off[i] = sm[w] + v - deg;
}

// atomic-free fill using precomputed slots
__global__ void csr_fill(EP ep) {
    int idx = blockIdx.x * blockDim.x + threadIdx.x;
    if (idx >= ETOT) return;
    int r = idx / E_PER, e = idx - r * E_PER;
    int gi = c_DOFF[r] + __ldg(&ep.d[r][e]);
    g_csrc[g_off[gi] + g_epos[idx]] = __ldg(&ep.s[r][e]);
}

// ---------------------------------- per-layer -----------------------------------

// both layers: block rl in [0,18): wsv[rl][k] = sum_j Wsrc[rl][k][j]*asrc[rl][j]
__global__ void prep(const float* __restrict__ Ws, const float* __restrict__ as_,
                     const float* __restrict__ Wd, const float* __restrict__ ad_) {
    int rl = blockIdx.x, t = threadIdx.x;
    const float* W; const float* a; float* o; int k;
    if (t < 64) { W = Ws + rl * 4096; a = as_ + rl * 64; o = g_wsv + rl * 64; k = t; }
    else        { W = Wd + rl * 4096; a = ad_ + rl * 64; o = g_wdv + rl * 64; k = t - 64; }
    float s = 0.f;
    #pragma unroll
    for (int j = 0; j < 64; j++) s += W[k * 64 + j] * a[j];
    o[k] = s;
}

// warp per node: attention logits for every (relation, side) of its type,
// plus fp16 conversion of the activated feature row into g_xh.
__global__ void alpha_all(XP xp, int use_feat, int wbase) {
    int warp = threadIdx.x >> 5, lane = threadIdx.x & 31;
    int gw = blockIdx.x * 8 + warp;
    if (gw >= NTOT) return;
    int t = (gw < N0) ? 0 : (gw < N0 + N1) ? 1 : (gw < N0 + N1 + N2) ? 2 : 3;
    int li = gw - c_OFF[t];
    const float2* x2 = (const float2*)(use_feat ? (g_feat0 + (size_t)c_OFF[t] * H)
                                                : xp.x[t]);
    float2 v = x2[(size_t)li * 32 + lane];          // elements 2*lane, 2*lane+1
    if (use_feat) { v.x = fmaxf(v.x, 0.f); v.y = fmaxf(v.y, 0.f); }
    g_xh[(size_t)gw * 32 + lane] = __float22half2_rn(v);
    #pragma unroll
    for (int r = 0; r < 9; r++) {
        if (c_ST[r] == t) {
            float2 w = ((const float2*)(g_wsv + wbase + r * 64))[lane];
            float s = v.x * w.x + v.y * w.y;
            #pragma unroll
            for (int o = 16; o; o >>= 1) s += __shfl_xor_sync(0xffffffffu, s, o);
            if (lane == 0) g_als[r * NMAX + li] = s;
        }
        int dt = (r < 3) ? (r + 1) : (r == 3 || r == 4) ? 3 : (r < 8) ? 0 : 2;
        if (dt == t) {
            float2 w = ((const float2*)(g_wdv + wbase + r * 64))[lane];
            float s = v.x * w.x + v.y * w.y;
            #pragma unroll
            for (int o = 16; o; o >>= 1) s += __shfl_xor_sync(0xffffffffu, s, o);
            if (lane == 0) g_ald[r * NMAX + li] = s;
        }
    }
}

// Fused gather + GEMM per dst-type tile of 32 rows. Gather reads fp16 rows
// (128B each) from g_xh, accumulates fp32, then 3xTF32 MMA accumulated across
// relations. Epilogue adds summed bias.
__global__ void __launch_bounds__(256) fused(const float* __restrict__ Ws_l,
                                             const float* __restrict__ bias_l,
                                             int outbuf) {
    __shared__ float sG[32 * 72];
    __shared__ float sW[64 * 72];
    __shared__ float sBias[64];
    int bx = blockIdx.x;
    int t = 0;
    #pragma unroll
    for (int i = 1; i < 4; i++) if (bx >= c_TILE0[i]) t = i;
    int row0 = (bx - c_TILE0[t]) * 32;
    int Nd = c_NSZ[t];
    int tid = threadIdx.x, warp = tid >> 5, lane = tid & 31;
    int grp = lane >> 3, lg = lane & 7;
    unsigned gmask = 0xFFu << (grp * 8);
    int nl = warp * 4 + grp;           // local node 0..31
    int d = row0 + nl;
    bool act = d < Nd;

    if (tid < 64) {
        float s = 0.f;
        #pragma unroll
        for (int i = 0; i < 3; i++) {
            int r = c_TB[t][i];
            if (r >= 0) s += bias_l[r * 64 + tid];
        }
        sBias[tid] = s;
    }

    int mrow = (warp & 1) * 16;
    int nh = warp >> 1;
    int gid = lane >> 2, tig = lane & 3;
    float acc[4][4];
    #pragma unroll
    for (int n = 0; n < 4; n++)
        #pragma unroll
        for (int j = 0; j < 4; j++) acc[n][j] = 0.f;

    #pragma unroll
    for (int ri = 0; ri < 3; ri++) {
        int r = c_TB[t][ri];
        if (r < 0) break;
        int st = c_ST[r];
        const __half2* xh = g_xh + (size_t)c_OFF[st] * 32;
        __syncthreads();               // previous MMA done with sG/sW

        const float4* W4 = (const float4*)(Ws_l + (size_t)r * 4096);
        #pragma unroll
        for (int i = 0; i < 4; i++) {
            int idx = tid + i * 256;
            int rr = idx >> 4, c4 = idx & 15;
            float4 v = W4[idx];
            float* dst = sW + rr * 72 + c4 * 4;
            dst[0] = v.x; dst[1] = v.y; dst[2] = v.z; dst[3] = v.w;
        }

        // ---- gather this node's neighbors for relation r (fp16 rows) ----
        float ald = 0.f; int beg = 0, deg = 0;
        if (act) {
            int gi = c_DOFF[r] + d;
            ald = __ldg(&g_ald[(size_t)r * NMAX + d]);
            beg = __ldg(&g_off[gi]);
            deg = __ldg(&g_deg[gi]);
        }
        const int* sl = g_csrc + beg;
        const float* als = g_als + (size_t)r * NMAX;

        float accA[8] = {0.f, 0.f, 0.f, 0.f, 0.f, 0.f, 0.f, 0.f};
        float accB[8] = {0.f, 0.f, 0.f, 0.f, 0.f, 0.f, 0.f, 0.f};
        float zl = 0.f;
        for (int base = 0; base < deg; base += 8) {
            int n = min(8, deg - base);
            int sidx = 0; float p = 0.f;
            if (lg < n) {
                sidx = __ldg(&sl[base + lg]);
                float sc = __ldg(&als[sidx]) + ald;
                sc = sc > 0.f ? sc : 0.2f * sc;
                p = __expf(sc);
            }
            zl += p;
            int i = 0;
            for (; i + 2 <= n; i += 2) {
                int   s0 = __shfl_sync(gmask, sidx, i,     8);
                int   s1 = __shfl_sync(gmask, sidx, i + 1, 8);
                float p0 = __shfl_sync(gmask, p,    i,     8);
                float p1 = __shfl_sync(gmask, p,    i + 1, 8);
                float4 q0 = ((const float4*)(xh + (size_t)s0 * 32))[lg];
                float4 q1 = ((const float4*)(xh + (size_t)s1 * 32))[lg];
                acc_h8(accA, q0, p0);
                acc_h8(accB, q1, p1);
            }
            if (i < n) {
                int   s0 = __shfl_sync(gmask, sidx, i, 8);
                float p0 = __shfl_sync(gmask, p,    i, 8);
                float4 q0 = ((const float4*)(xh + (size_t)s0 * 32))[lg];
                acc_h8(accA, q0, p0);
            }
        }
        #pragma unroll
        for (int o = 4; o; o >>= 1) zl += __shfl_xor_sync(gmask, zl, o, 8);
        float inv = act ? __fdividef(1.f, zl + 1e-16f) : 0.f;
        float* gr = sG + nl * 72 + lg * 8;
        ((float4*)gr)[0] = make_float4((accA[0] + accB[0]) * inv, (accA[1] + accB[1]) * inv,
                                       (accA[2] + accB[2]) * inv, (accA[3] + accB[3]) * inv);
        ((float4*)gr)[1] = make_float4((accA[4] + accB[4]) * inv, (accA[5] + accB[5]) * inv,
                                       (accA[6] + accB[6]) * inv, (accA[7] + accB[7]) * inv);
        __syncthreads();

        // ---- 3xTF32 MMA: acc += sG @ W_r ----
        if (warp < 4) {
            #pragma unroll
            for (int k0 = 0; k0 < 8; k0++) {
                float af[4];
                af[0] = sG[(mrow + gid)     * 72 + k0 * 8 + tig];
                af[1] = sG[(mrow + gid + 8) * 72 + k0 * 8 + tig];
                af[2] = sG[(mrow + gid)     * 72 + k0 * 8 + tig + 4];
                af[3] = sG[(mrow + gid + 8) * 72 + k0 * 8 + tig + 4];
                unsigned as_[4], ar_[4];
                #pragma unroll
                for (int j = 0; j < 4; j++) {
                    as_[j] = f2tf(af[j]);
                    ar_[j] = f2tf(af[j] - __uint_as_float(as_[j]));
                }
                #pragma unroll
                for (int n0 = 0; n0 < 4; n0++) {
                    int nc = (nh * 4 + n0) * 8 + gid;
                    float bf0 = sW[(k0 * 8 + tig)     * 72 + nc];
                    float bf1 = sW[(k0 * 8 + tig + 4) * 72 + nc];
                    unsigned bs0 = f2tf(bf0), bs1 = f2tf(bf1);
                    unsigned br0 = f2tf(bf0 - __uint_as_float(bs0));
                    unsigned br1 = f2tf(bf1 - __uint_as_float(bs1));
                    mma8(acc[n0], as_, bs0, bs1);
                    mma8(acc[n0], ar_, bs0, bs1);
                    mma8(acc[n0], as_, br0, br1);
                }
            }
        }
    }

    if (warp < 4) {
        float* fb = ((outbuf == 0) ? g_feat0 : g_feat1) + (size_t)c_OFF[t] * H;
        int rr0 = row0 + mrow + gid;
        int rr1 = rr0 + 8;
        #pragma unroll
        for (int n0 = 0; n0 < 4; n0++) {
            int cc = (nh * 4 + n0) * 8 + 2 * tig;
            float bv0 = sBias[cc], bv1 = sBias[cc + 1];
            if (rr0 < Nd) {
                float2* p = (float2*)(fb + (size_t)rr0 * H + cc);
                *p = make_float2(acc[n0][0] + bv0, acc[n0][1] + bv1);
            }
            if (rr1 < Nd) {
                float2* p = (float2*)(fb + (size_t)rr1 * H + cc);
                *p = make_float2(acc[n0][2] + bv0, acc[n0][3] + bv1);
            }
        }
    }
}

// ---------------------------------- pooling -------------------------------------
#define NPW 16
__global__ void pool_kernel(const int* __restrict__ bvar, const int* __restrict__ bcon) {
    int warp = threadIdx.x >> 5, lane = threadIdx.x & 31;
    int gw = blockIdx.x * 8 + warp;
    const int nvw = (N0 + NPW - 1) / NPW;
    const int ncw = (N3 + NPW - 1) / NPW;
    if (gw < nvw) {
        int i0 = gw * NPW, i1 = min(N0, i0 + NPW);
        float a0 = 0.f, a1 = 0.f; float cnt = 0.f;
        int curb = __ldg(&bvar[i0]);
        for (int i = i0; i < i1; i++) {
            int b = __ldg(&bvar[i]);
            if (b != curb) {
                atomicAdd(&g_pool[curb * 128 + lane], a0);
                atomicAdd(&g_pool[curb * 128 + 32 + lane], a1);
                if (lane == 0) atomicAdd(&g_cnt[curb], cnt);
                a0 = a1 = 0.f; cnt = 0.f; curb = b;
            }
            size_t base = (size_t)i * H;
            a0 += fmaxf(g_feat1[base + lane], 0.f);
            a1 += fmaxf(g_feat1[base + 32 + lane], 0.f);
            cnt += 1.f;
        }
        atomicAdd(&g_pool[curb * 128 + lane], a0);
        atomicAdd(&g_pool[curb * 128 + 32 + lane], a1);
        if (lane == 0) atomicAdd(&g_cnt[curb], cnt);
    } else if (gw < nvw + ncw) {
        int gj = gw - nvw;
        const float* xc = g_feat1 + (size_t)(N0 + N1 + N2) * H;
        int i0 = gj * NPW, i1 = min(N3, i0 + NPW);
        float a0 = 0.f, a1 = 0.f; float cnt = 0.f;
        int curb = __ldg(&bcon[i0]);
        for (int i = i0; i < i1; i++) {
            int b = __ldg(&bcon[i]);
            if (b != curb) {
                atomicAdd(&g_pool[curb * 128 + 64 + lane], a0);
                atomicAdd(&g_pool[curb * 128 + 96 + lane], a1);
                if (lane == 0) atomicAdd(&g_cnt[NB + curb], cnt);
                a0 = a1 = 0.f; cnt = 0.f; curb = b;
            }
            size_t base = (size_t)i * H;
            a0 += fmaxf(xc[base + lane], 0.f);
            a1 += fmaxf(xc[base + 32 + lane], 0.f);
            cnt += 1.f;
        }
        atomicAdd(&g_pool[curb * 128 + 64 + lane], a0);
        atomicAdd(&g_pool[curb * 128 + 96 + lane], a1);
        if (lane == 0) atomicAdd(&g_cnt[NB + curb], cnt);
    }
}

__global__ void final_kernel(const float* __restrict__ lw, const float* __restrict__ lb,
                             float* __restrict__ out) {
    int t = threadIdx.x;
    if (t >= 128) return;
    int b = t >> 1, o = t & 1;
    float cv = fmaxf(g_cnt[b], 1.f);
    float cc = fmaxf(g_cnt[NB + b], 1.f);
    float s = lb[o];
    #pragma unroll
    for (int j = 0; j < H; j++) {
        s += (g_pool[b * 128 + j]      / cv) * lw[o * 128 + j];
        s += (g_pool[b * 128 + 64 + j] / cc) * lw[o * 128 + 64 + j];
    }
    out[b * 2 + o] = s;
}

// ---------------------------------- launcher -------------------------------------
extern "C" void kernel_launch(void* const* d_in, const int* in_sizes, int n_in,
                              void* d_out, int out_size) {
    XP xp;
    for (int t = 0; t < 4; t++) xp.x[t] = (const float*)d_in[t];
    const float* Wsrc = (const float*)d_in[4];
    const float* Wdst = (const float*)d_in[5];
    const float* asrc = (const float*)d_in[6];
    const float* adst = (const float*)d_in[7];
    const float* bias = (const float*)d_in[8];
    const float* lw   = (const float*)d_in[9];
    const float* lb   = (const float*)d_in[10];
    EP ep;
    for (int r = 0; r < 9; r++) {
        ep.s[r] = (const int*)d_in[11 + 2 * r];
        ep.d[r] = (const int*)d_in[12 + 2 * r];
    }
    const int* bvar = (const int*)d_in[29];
    const int* bcon = (const int*)d_in[30];

    // CSR build (edges are constant; rebuilt identically every call)
    csr_zero<<<(NDSUM + 255) / 256, 256>>>();
    csr_hist<<<(ETOT + 255) / 256, 256>>>(ep);
    csr_assign<<<(NDSUM + 255) / 256, 256>>>();
    csr_fill<<<(ETOT + 255) / 256, 256>>>(ep);
    prep<<<18, 128>>>(Wsrc, asrc, Wdst, adst);

    for (int l = 0; l < 2; l++) {
        const float* Ws_l = Wsrc + (size_t)l * 9 * 4096;
        const float* b_l  = bias + (size_t)l * 9 * 64;
        alpha_all<<<(NTOT + 7) / 8, 256>>>(xp, l, l * 9 * 64);
        fused<<<7813, 256>>>(Ws_l, b_l, l);
    }
    pool_kernel<<<((N0 + NPW - 1) / NPW + (N3 + NPW - 1) / NPW + 7) / 8, 256>>>(bvar, bcon);
    final_kernel<<<1, 128>>>(lw, lb, (float*)d_out);
}